// round 4
// baseline (speedup 1.0000x reference)
#include <cuda_runtime.h>
#include <cuda_bf16.h>
#include <math.h>

// Problem constants
#define QM 8
#define VV 6890
#define KN 16
#define EE 256
#define HH 8
#define DD 32
#define NTOK (QM * VV)          // 55120
#define FF (4 * EE)             // 1024

// Scratch (static device globals; no runtime allocation)
__device__ float g_qkv[(size_t)NTOK * 768];   // [N][q|k|v]
__device__ float g_o[(size_t)NTOK * EE];      // attention output
__device__ float g_x[(size_t)NTOK * EE];      // post-LN1 x (residual for FFN)
__device__ float g_h[(size_t)NTOK * FF];      // GELU(FFN1)

// Canonicalized index/mask buffers + dtype flags
__device__ int g_idx64;
__device__ int g_mask32;
__device__ int g_cidx[(size_t)NTOK * KN];     // b*V + g as int32
__device__ unsigned char g_cmask[(size_t)NTOK * KN];

// ---------------------------------------------------------------------------
// Dtype detection (deterministic; sample-based with ~0 misdetection prob)
// ---------------------------------------------------------------------------
__global__ void detect_kernel(const void* bidx, const void* mask)
{
    __shared__ int s_is64, s_m32;
    if (threadIdx.x == 0) { s_is64 = 1; s_m32 = 1; }
    __syncthreads();

    const unsigned long long* b64 = (const unsigned long long*)bidx;
    for (int i = threadIdx.x; i < 1024; i += blockDim.x)
        if (b64[i] >= (1ull << 32)) atomicExch(&s_is64, 0);

    const unsigned int* m32 = (const unsigned int*)mask;
    for (int i = threadIdx.x; i < 1024; i += blockDim.x)
        if (m32[i] > 1u) atomicExch(&s_m32, 0);

    __syncthreads();
    if (threadIdx.x == 0) { g_idx64 = s_is64; g_mask32 = s_m32; }
}

__global__ void convert_kernel(const void* bidx, const void* graph, const void* mask)
{
    const int is64 = g_idx64;
    const int m32  = g_mask32;
    const int total = NTOK * KN;
    for (int i = blockIdx.x * blockDim.x + threadIdx.x; i < total;
         i += gridDim.x * blockDim.x) {
        int b, g;
        if (is64) {
            b = (int)((const long long*)bidx)[i];
            g = (int)((const long long*)graph)[i];
        } else {
            b = ((const int*)bidx)[i];
            g = ((const int*)graph)[i];
        }
        g_cidx[i] = b * VV + g;
        g_cmask[i] = m32 ? (unsigned char)(((const int*)mask)[i] != 0)
                         : ((const unsigned char*)mask)[i];
    }
}

// ---------------------------------------------------------------------------
// Packed fp32x2 FMA helpers (Blackwell FFMA2 — exact fp32 math, 2 FMA/instr)
// ---------------------------------------------------------------------------
__device__ __forceinline__ void ffma2(unsigned long long& d,
                                      unsigned long long a,
                                      unsigned long long b) {
    asm("fma.rn.f32x2 %0, %1, %2, %0;" : "+l"(d) : "l"(a), "l"(b));
}
__device__ __forceinline__ unsigned long long pack2(float x) {
    unsigned long long r;
    asm("mov.b64 %0, {%1, %1};" : "=l"(r) : "f"(x));
    return r;
}
__device__ __forceinline__ void unpack2(unsigned long long v, float& lo, float& hi) {
    asm("mov.b64 {%0, %1}, %2;" : "=f"(lo), "=f"(hi) : "l"(v));
}

__device__ __forceinline__ float gelu_exact(float x) {
    return 0.5f * x * (1.0f + erff(x * 0.7071067811865475f));
}

// ---------------------------------------------------------------------------
// GEMM: C[M, Ncols] = A[M, Kd] @ W[Ncols, Kd]^T + bias (+ res) (GELU optional)
// BM=BN=128, BK=16, TM=TN=8, 256 threads. Double-buffered smem + FFMA2 core.
// ---------------------------------------------------------------------------
template<bool HASRES, bool DOGELU>
__global__ void __launch_bounds__(256)
gemm_kernel(const float* __restrict__ A, const float* __restrict__ W,
            const float* __restrict__ bias, float* __restrict__ C,
            const float* __restrict__ res,
            int M, int Kd, int ldc)
{
    __shared__ __align__(16) float As[2][16][132];
    __shared__ __align__(16) float Bs[2][16][132];

    const int tid = threadIdx.x;
    const int tx = tid & 15;
    const int ty = tid >> 4;
    const int row0 = blockIdx.x * 128;
    const int col0 = blockIdx.y * 128;

    unsigned long long acc2[8][4];
#pragma unroll
    for (int i = 0; i < 8; i++)
#pragma unroll
        for (int j = 0; j < 4; j++) acc2[i][j] = 0ull;

    const int lm  = tid >> 2;        // 0..63
    const int lk4 = (tid & 3) * 4;   // 0,4,8,12
    const int nIter = Kd / 16;

    // Preload tile 0 into buffer 0
    {
#pragma unroll
        for (int half = 0; half < 2; half++) {
            const int m = lm + half * 64;
            const int r = row0 + m;
            float4 av = make_float4(0.f, 0.f, 0.f, 0.f);
            if (r < M) av = *(const float4*)(A + (size_t)r * Kd + lk4);
            As[0][lk4 + 0][m] = av.x;
            As[0][lk4 + 1][m] = av.y;
            As[0][lk4 + 2][m] = av.z;
            As[0][lk4 + 3][m] = av.w;

            float4 bv = *(const float4*)(W + (size_t)(col0 + m) * Kd + lk4);
            Bs[0][lk4 + 0][m] = bv.x;
            Bs[0][lk4 + 1][m] = bv.y;
            Bs[0][lk4 + 2][m] = bv.z;
            Bs[0][lk4 + 3][m] = bv.w;
        }
    }
    __syncthreads();

    for (int it = 0; it < nIter; it++) {
        const int cur = it & 1;
        const int nxt = cur ^ 1;
        const bool has_next = (it + 1 < nIter);

        // Prefetch next tile gmem -> regs
        float4 pa[2], pb[2];
        if (has_next) {
            const int kb = (it + 1) * 16;
#pragma unroll
            for (int half = 0; half < 2; half++) {
                const int m = lm + half * 64;
                const int r = row0 + m;
                pa[half] = make_float4(0.f, 0.f, 0.f, 0.f);
                if (r < M) pa[half] = *(const float4*)(A + (size_t)r * Kd + kb + lk4);
                pb[half] = *(const float4*)(W + (size_t)(col0 + m) * Kd + kb + lk4);
            }
        }

        // Compute on current buffer (FFMA2 core)
#pragma unroll
        for (int k = 0; k < 16; k++) {
            float a[8];
            *(float4*)(a)     = *(const float4*)&As[cur][k][ty * 8];
            *(float4*)(a + 4) = *(const float4*)&As[cur][k][ty * 8 + 4];
            const double2 bA = *(const double2*)&Bs[cur][k][tx * 8];
            const double2 bB = *(const double2*)&Bs[cur][k][tx * 8 + 4];
            unsigned long long b2[4];
            b2[0] = __double_as_longlong(bA.x);
            b2[1] = __double_as_longlong(bA.y);
            b2[2] = __double_as_longlong(bB.x);
            b2[3] = __double_as_longlong(bB.y);
#pragma unroll
            for (int i = 0; i < 8; i++) {
                const unsigned long long a2 = pack2(a[i]);
#pragma unroll
                for (int j = 0; j < 4; j++) ffma2(acc2[i][j], a2, b2[j]);
            }
        }

        // Store prefetched tile regs -> next buffer
        if (has_next) {
#pragma unroll
            for (int half = 0; half < 2; half++) {
                const int m = lm + half * 64;
                As[nxt][lk4 + 0][m] = pa[half].x;
                As[nxt][lk4 + 1][m] = pa[half].y;
                As[nxt][lk4 + 2][m] = pa[half].z;
                As[nxt][lk4 + 3][m] = pa[half].w;
                Bs[nxt][lk4 + 0][m] = pb[half].x;
                Bs[nxt][lk4 + 1][m] = pb[half].y;
                Bs[nxt][lk4 + 2][m] = pb[half].z;
                Bs[nxt][lk4 + 3][m] = pb[half].w;
            }
        }
        __syncthreads();
    }

#pragma unroll
    for (int i = 0; i < 8; i++) {
        const int r = row0 + ty * 8 + i;
        if (r >= M) continue;
#pragma unroll
        for (int j = 0; j < 4; j++) {
            float v0, v1;
            unpack2(acc2[i][j], v0, v1);
            const int cg = col0 + tx * 8 + j * 2;
            v0 += bias[cg];
            v1 += bias[cg + 1];
            if (HASRES) {
                v0 += res[(size_t)r * ldc + cg];
                v1 += res[(size_t)r * ldc + cg + 1];
            }
            if (DOGELU) { v0 = gelu_exact(v0); v1 = gelu_exact(v1); }
            C[(size_t)r * ldc + cg]     = v0;
            C[(size_t)r * ldc + cg + 1] = v1;
        }
    }
}

// ---------------------------------------------------------------------------
// Attention: one block per token n (256 threads = 8 warps = 8 heads).
// ---------------------------------------------------------------------------
__global__ void __launch_bounds__(256)
attn_kernel(const float* __restrict__ qkv, float* __restrict__ o)
{
    const int n = blockIdx.x;
    __shared__ int s_m[KN];
    __shared__ unsigned char s_mask[KN];

    const int tid = threadIdx.x;
    if (tid < KN) {
        s_m[tid] = g_cidx[(size_t)n * KN + tid];
        s_mask[tid] = g_cmask[(size_t)n * KN + tid];
    }
    __syncthreads();

    const int h = tid >> 5;
    const int lane = tid & 31;
    const int hofs = h * DD + lane;

    const float qv = qkv[(size_t)n * 768 + hofs];

    float sc[KN];
#pragma unroll
    for (int k = 0; k < KN; k++) {
        float p = qv * qkv[(size_t)s_m[k] * 768 + 256 + hofs];
        p += __shfl_xor_sync(0xffffffffu, p, 16);
        p += __shfl_xor_sync(0xffffffffu, p, 8);
        p += __shfl_xor_sync(0xffffffffu, p, 4);
        p += __shfl_xor_sync(0xffffffffu, p, 2);
        p += __shfl_xor_sync(0xffffffffu, p, 1);
        sc[k] = p;
    }

    const float NEGINF = __int_as_float(0xff800000);
    float mx = NEGINF;
#pragma unroll
    for (int k = 0; k < KN; k++) {
        sc[k] = s_mask[k] ? NEGINF : sc[k] * 0.1767766952966369f; // 1/sqrt(32)
        mx = fmaxf(mx, sc[k]);
    }
    float sum = 0.0f;
#pragma unroll
    for (int k = 0; k < KN; k++) {
        sc[k] = __expf(sc[k] - mx);
        sum += sc[k];
    }
    const float inv = 1.0f / sum;

    float accv = 0.0f;
#pragma unroll
    for (int k = 0; k < KN; k++)
        accv = fmaf(sc[k], qkv[(size_t)s_m[k] * 768 + 512 + hofs], accv);

    o[(size_t)n * EE + hofs] = accv * inv;
}

// ---------------------------------------------------------------------------
// LayerNorm over E=256, warp per row (8 elems/lane), in-place.
// ---------------------------------------------------------------------------
__global__ void __launch_bounds__(256)
ln_kernel(float* __restrict__ X, const float* __restrict__ gamma,
          const float* __restrict__ beta, int rows)
{
    const int row = blockIdx.x * 8 + (threadIdx.x >> 5);
    if (row >= rows) return;
    const int lane = threadIdx.x & 31;
    float* xr = X + (size_t)row * EE;

    float v[8];
    float s = 0.0f;
#pragma unroll
    for (int i = 0; i < 8; i++) {
        v[i] = xr[lane + i * 32];
        s += v[i];
    }
#pragma unroll
    for (int d = 16; d > 0; d >>= 1) s += __shfl_xor_sync(0xffffffffu, s, d);
    const float mean = s * (1.0f / 256.0f);

    float var = 0.0f;
#pragma unroll
    for (int i = 0; i < 8; i++) {
        const float d = v[i] - mean;
        var = fmaf(d, d, var);
    }
#pragma unroll
    for (int d = 16; d > 0; d >>= 1) var += __shfl_xor_sync(0xffffffffu, var, d);
    const float rstd = rsqrtf(var * (1.0f / 256.0f) + 1e-5f);

#pragma unroll
    for (int i = 0; i < 8; i++) {
        const int c = lane + i * 32;
        xr[c] = (v[i] - mean) * rstd * gamma[c] + beta[c];
    }
}

// ---------------------------------------------------------------------------
extern "C" void kernel_launch(void* const* d_in, const int* in_sizes, int n_in,
                              void* d_out, int out_size)
{
    const float* mq    = (const float*)d_in[0];
    const float* Wq    = (const float*)d_in[1];
    const float* bq    = (const float*)d_in[2];
    const float* Wk    = (const float*)d_in[3];
    const float* bk    = (const float*)d_in[4];
    const float* Wv    = (const float*)d_in[5];
    const float* bv    = (const float*)d_in[6];
    const float* Wo    = (const float*)d_in[7];
    const float* bo    = (const float*)d_in[8];
    const float* ln1g  = (const float*)d_in[9];
    const float* ln1b  = (const float*)d_in[10];
    const float* W1    = (const float*)d_in[11];
    const float* b1    = (const float*)d_in[12];
    const float* W2    = (const float*)d_in[13];
    const float* b2    = (const float*)d_in[14];
    const float* ln2g  = (const float*)d_in[15];
    const float* ln2b  = (const float*)d_in[16];
    const void*  bidx  = d_in[17];
    const void*  graph = d_in[18];
    const void*  mask  = d_in[19];

    float* out = (float*)d_out;

    float* qkv; cudaGetSymbolAddress((void**)&qkv, g_qkv);
    float* o;   cudaGetSymbolAddress((void**)&o,   g_o);
    float* x;   cudaGetSymbolAddress((void**)&x,   g_x);
    float* hbuf;cudaGetSymbolAddress((void**)&hbuf,g_h);

    const int M = NTOK;
    const int MB = (M + 127) / 128;   // 431

    // 0) Detect index/mask dtypes and canonicalize
    detect_kernel<<<1, 256>>>(bidx, mask);
    convert_kernel<<<256, 256>>>(bidx, graph, mask);

    // 1) Q/K/V projections of ALL vertices (project-then-gather)
    {
        dim3 grid(MB, 2);
        gemm_kernel<false, false><<<grid, 256>>>(mq, Wq, bq, qkv + 0,   nullptr, M, EE, 768);
        gemm_kernel<false, false><<<grid, 256>>>(mq, Wk, bk, qkv + 256, nullptr, M, EE, 768);
        gemm_kernel<false, false><<<grid, 256>>>(mq, Wv, bv, qkv + 512, nullptr, M, EE, 768);
    }

    // 2) Attention with gathered K/V rows
    attn_kernel<<<M, 256>>>(qkv, o);

    // 3) Wo projection + residual(mq) -> x_pre, then LN1 in-place
    {
        dim3 grid(MB, 2);
        gemm_kernel<true, false><<<grid, 256>>>(o, Wo, bo, x, mq, M, EE, EE);
        ln_kernel<<<(M + 7) / 8, 256>>>(x, ln1g, ln1b, M);
    }

    // 4) FFN1 + exact GELU
    {
        dim3 grid(MB, 8);
        gemm_kernel<false, true><<<grid, 256>>>(x, W1, b1, hbuf, nullptr, M, EE, FF);
    }

    // 5) FFN2 + residual(x) -> out, then LN2 in-place
    {
        dim3 grid(MB, 2);
        gemm_kernel<true, false><<<grid, 256>>>(hbuf, W2, b2, out, x, M, FF, EE);
        ln_kernel<<<(M + 7) / 8, 256>>>(out, ln2g, ln2b, M);
    }
}

// round 6
// speedup vs baseline: 1.5246x; 1.5246x over previous
#include <cuda_runtime.h>
#include <cuda_bf16.h>
#include <math.h>
#include <stdint.h>

// Problem constants
#define QM 8
#define VV 6890
#define KN 16
#define EE 256
#define HH 8
#define DD 32
#define NTOK (QM * VV)          // 55120
#define FF (4 * EE)             // 1024

// GEMM tiling
#define BM 128
#define BN 128
#define BK 32
#define SKP 40                  // smem row stride in halves (32 + 8 pad)

// Scratch (static device globals; no runtime allocation)
__device__ float g_qkv[(size_t)NTOK * 768];   // [N][q|k|v]
__device__ float g_o[(size_t)NTOK * EE];      // attention output
__device__ float g_x[(size_t)NTOK * EE];      // post-LN1 x (residual for FFN)
__device__ float g_h[(size_t)NTOK * FF];      // GELU(FFN1)

// Canonicalized index/mask buffers + dtype flags
__device__ int g_idx64;
__device__ int g_mask32;
__device__ int g_cidx[(size_t)NTOK * KN];
__device__ unsigned char g_cmask[(size_t)NTOK * KN];

// ---------------------------------------------------------------------------
// Dtype detection (deterministic; sample-based with ~0 misdetection prob)
// ---------------------------------------------------------------------------
__global__ void detect_kernel(const void* bidx, const void* mask)
{
    __shared__ int s_is64, s_m32;
    if (threadIdx.x == 0) { s_is64 = 1; s_m32 = 1; }
    __syncthreads();

    const unsigned long long* b64 = (const unsigned long long*)bidx;
    for (int i = threadIdx.x; i < 1024; i += blockDim.x)
        if (b64[i] >= (1ull << 32)) atomicExch(&s_is64, 0);

    const unsigned int* m32 = (const unsigned int*)mask;
    for (int i = threadIdx.x; i < 1024; i += blockDim.x)
        if (m32[i] > 1u) atomicExch(&s_m32, 0);

    __syncthreads();
    if (threadIdx.x == 0) { g_idx64 = s_is64; g_mask32 = s_m32; }
}

__global__ void convert_kernel(const void* bidx, const void* graph, const void* mask)
{
    const int is64 = g_idx64;
    const int m32  = g_mask32;
    const int total = NTOK * KN;
    for (int i = blockIdx.x * blockDim.x + threadIdx.x; i < total;
         i += gridDim.x * blockDim.x) {
        int b, g;
        if (is64) {
            b = (int)((const long long*)bidx)[i];
            g = (int)((const long long*)graph)[i];
        } else {
            b = ((const int*)bidx)[i];
            g = ((const int*)graph)[i];
        }
        g_cidx[i] = b * VV + g;
        g_cmask[i] = m32 ? (unsigned char)(((const int*)mask)[i] != 0)
                         : ((const unsigned char*)mask)[i];
    }
}

// ---------------------------------------------------------------------------
// MMA helpers
// ---------------------------------------------------------------------------
__device__ __forceinline__ uint32_t smem_u32(const void* p) {
    return (uint32_t)__cvta_generic_to_shared(p);
}
__device__ __forceinline__ void ldsm_x4(uint32_t& r0, uint32_t& r1,
                                        uint32_t& r2, uint32_t& r3, uint32_t addr) {
    asm volatile("ldmatrix.sync.aligned.m8n8.x4.shared.b16 {%0,%1,%2,%3}, [%4];"
                 : "=r"(r0), "=r"(r1), "=r"(r2), "=r"(r3) : "r"(addr));
}
__device__ __forceinline__ void ldsm_x2(uint32_t& r0, uint32_t& r1, uint32_t addr) {
    asm volatile("ldmatrix.sync.aligned.m8n8.x2.shared.b16 {%0,%1}, [%2];"
                 : "=r"(r0), "=r"(r1) : "r"(addr));
}
__device__ __forceinline__ void mma_bf16(float* d, const uint32_t* a, const uint32_t* b) {
    asm volatile("mma.sync.aligned.m16n8k16.row.col.f32.bf16.bf16.f32 "
                 "{%0,%1,%2,%3}, {%4,%5,%6,%7}, {%8,%9}, {%0,%1,%2,%3};"
                 : "+f"(d[0]), "+f"(d[1]), "+f"(d[2]), "+f"(d[3])
                 : "r"(a[0]), "r"(a[1]), "r"(a[2]), "r"(a[3]), "r"(b[0]), "r"(b[1]));
}

__device__ __forceinline__ float gelu_exact(float x) {
    return 0.5f * x * (1.0f + erff(x * 0.7071067811865475f));
}

// ---------------------------------------------------------------------------
// Split-bf16 tensor-core GEMM (3-product fp32 emulation).
// C[M, *] = A[M,Kd] @ W[Ncols,Kd]^T + bias (+res) (gelu opt).
// Grid: (ceil(M/128), Ncols/128, nz). z selects weight/bias; out col offset
// = z*zstride + weight-local col. 256 threads = 8 warps, warp tile 64x32.
// ---------------------------------------------------------------------------
template<bool HASRES, bool DOGELU>
__global__ void __launch_bounds__(256)
gemm_tc(const float* __restrict__ A,
        const float* __restrict__ Wa, const float* __restrict__ Wb,
        const float* __restrict__ Wc,
        const float* __restrict__ ba, const float* __restrict__ bb,
        const float* __restrict__ bc,
        float* __restrict__ C, const float* __restrict__ res,
        int M, int Kd, int ldc, int zstride)
{
    __shared__ __nv_bfloat16 sAh[BM * SKP];
    __shared__ __nv_bfloat16 sAl[BM * SKP];
    __shared__ __nv_bfloat16 sBh[BN * SKP];
    __shared__ __nv_bfloat16 sBl[BN * SKP];

    const int z = blockIdx.z;
    const float* W    = (z == 0) ? Wa : (z == 1) ? Wb : Wc;
    const float* bias = (z == 0) ? ba : (z == 1) ? bb : bc;

    const int tid = threadIdx.x;
    const int lane = tid & 31;
    const int warp = tid >> 5;
    const int warpRow = warp >> 2;       // 0..1
    const int warpCol = warp & 3;        // 0..3
    const int wm0 = warpRow * 64;
    const int wn0 = warpCol * 32;

    const int row0 = blockIdx.x * BM;
    const int wcol0 = blockIdx.y * BN;             // column within W
    const int outbase = z * zstride;               // column offset in C

    // Loader mapping: 2 threads per row, 16 k each (4 float4)
    const int lrow = tid >> 1;
    const int lk0  = (tid & 1) * 16;

    float acc[4][4][4];
#pragma unroll
    for (int mi = 0; mi < 4; mi++)
#pragma unroll
        for (int ni = 0; ni < 4; ni++)
#pragma unroll
            for (int r = 0; r < 4; r++) acc[mi][ni][r] = 0.0f;

    const int nIter = Kd / BK;

    // ldmatrix smem addresses (constant per thread, advanced by k2)
    const int aRow = wm0 + (lane & 15);
    const int aKoff = (lane >> 4) * 8;
    const int bLane = lane & 15;
    const int bRowB = wn0 + (bLane & 7);
    const int bKoff = (bLane >> 3) * 8;

    for (int it = 0; it < nIter; it++) {
        const int kb = it * BK;
        // ---- load + split-convert A and B tiles ----
#pragma unroll
        for (int i = 0; i < 4; i++) {
            const int kk = lk0 + i * 4;
            float4 av = make_float4(0.f, 0.f, 0.f, 0.f);
            const int r = row0 + lrow;
            if (r < M) av = *(const float4*)(A + (size_t)r * Kd + kb + kk);
            float4 bv = *(const float4*)(W + (size_t)(wcol0 + lrow) * Kd + kb + kk);

            const float af[4] = {av.x, av.y, av.z, av.w};
            const float bf[4] = {bv.x, bv.y, bv.z, bv.w};
            __nv_bfloat162 ah2[2], al2[2], bh2[2], bl2[2];
#pragma unroll
            for (int p = 0; p < 2; p++) {
                __nv_bfloat16 h0 = __float2bfloat16(af[2*p]);
                __nv_bfloat16 h1 = __float2bfloat16(af[2*p+1]);
                ah2[p] = __nv_bfloat162(h0, h1);
                al2[p] = __nv_bfloat162(
                    __float2bfloat16(af[2*p]   - __bfloat162float(h0)),
                    __float2bfloat16(af[2*p+1] - __bfloat162float(h1)));
                __nv_bfloat16 g0 = __float2bfloat16(bf[2*p]);
                __nv_bfloat16 g1 = __float2bfloat16(bf[2*p+1]);
                bh2[p] = __nv_bfloat162(g0, g1);
                bl2[p] = __nv_bfloat162(
                    __float2bfloat16(bf[2*p]   - __bfloat162float(g0)),
                    __float2bfloat16(bf[2*p+1] - __bfloat162float(g1)));
            }
            const int so = lrow * SKP + kk;
            *(__nv_bfloat162*)&sAh[so]     = ah2[0];
            *(__nv_bfloat162*)&sAh[so + 2] = ah2[1];
            *(__nv_bfloat162*)&sAl[so]     = al2[0];
            *(__nv_bfloat162*)&sAl[so + 2] = al2[1];
            *(__nv_bfloat162*)&sBh[so]     = bh2[0];
            *(__nv_bfloat162*)&sBh[so + 2] = bh2[1];
            *(__nv_bfloat162*)&sBl[so]     = bl2[0];
            *(__nv_bfloat162*)&sBl[so + 2] = bl2[1];
        }
        __syncthreads();

        // ---- compute: 2 k-steps of 16 ----
#pragma unroll
        for (int k2 = 0; k2 < BK; k2 += 16) {
            uint32_t ah[4][4], al[4][4], bh[4][2], bl[4][2];
#pragma unroll
            for (int mi = 0; mi < 4; mi++) {
                const int off = ((aRow + mi * 16) * SKP + k2 + aKoff) * 2;
                ldsm_x4(ah[mi][0], ah[mi][1], ah[mi][2], ah[mi][3],
                        smem_u32(sAh) + off);
                ldsm_x4(al[mi][0], al[mi][1], al[mi][2], al[mi][3],
                        smem_u32(sAl) + off);
            }
#pragma unroll
            for (int ni = 0; ni < 4; ni++) {
                const int off = ((bRowB + ni * 8) * SKP + k2 + bKoff) * 2;
                ldsm_x2(bh[ni][0], bh[ni][1], smem_u32(sBh) + off);
                ldsm_x2(bl[ni][0], bl[ni][1], smem_u32(sBl) + off);
            }
#pragma unroll
            for (int mi = 0; mi < 4; mi++)
#pragma unroll
                for (int ni = 0; ni < 4; ni++) {
                    mma_bf16(acc[mi][ni], ah[mi], bh[ni]);
                    mma_bf16(acc[mi][ni], ah[mi], bl[ni]);
                    mma_bf16(acc[mi][ni], al[mi], bh[ni]);
                }
        }
        __syncthreads();
    }

    // ---- epilogue ----
#pragma unroll
    for (int mi = 0; mi < 4; mi++) {
#pragma unroll
        for (int ni = 0; ni < 4; ni++) {
            const int rA = row0 + wm0 + mi * 16 + (lane >> 2);
            // weight-local column (bias index), and global output column
            const int cw = wcol0 + wn0 + ni * 8 + 2 * (lane & 3);
            const int cg = outbase + cw;
            const float b0 = bias[cw], b1 = bias[cw + 1];
#pragma unroll
            for (int half = 0; half < 2; half++) {
                const int r = rA + half * 8;
                if (r >= M) continue;
                float v0 = acc[mi][ni][half * 2 + 0] + b0;
                float v1 = acc[mi][ni][half * 2 + 1] + b1;
                if (HASRES) {
                    v0 += res[(size_t)r * ldc + cg];
                    v1 += res[(size_t)r * ldc + cg + 1];
                }
                if (DOGELU) { v0 = gelu_exact(v0); v1 = gelu_exact(v1); }
                *(float2*)(C + (size_t)r * ldc + cg) = make_float2(v0, v1);
            }
        }
    }
}

// ---------------------------------------------------------------------------
// Attention: one block per token n (256 threads = 8 warps = 8 heads).
// ---------------------------------------------------------------------------
__global__ void __launch_bounds__(256)
attn_kernel(const float* __restrict__ qkv, float* __restrict__ o)
{
    const int n = blockIdx.x;
    __shared__ int s_m[KN];
    __shared__ unsigned char s_mask[KN];

    const int tid = threadIdx.x;
    if (tid < KN) {
        s_m[tid] = g_cidx[(size_t)n * KN + tid];
        s_mask[tid] = g_cmask[(size_t)n * KN + tid];
    }
    __syncthreads();

    const int h = tid >> 5;
    const int lane = tid & 31;
    const int hofs = h * DD + lane;

    const float qv = qkv[(size_t)n * 768 + hofs];

    float sc[KN];
#pragma unroll
    for (int k = 0; k < KN; k++) {
        float p = qv * qkv[(size_t)s_m[k] * 768 + 256 + hofs];
        p += __shfl_xor_sync(0xffffffffu, p, 16);
        p += __shfl_xor_sync(0xffffffffu, p, 8);
        p += __shfl_xor_sync(0xffffffffu, p, 4);
        p += __shfl_xor_sync(0xffffffffu, p, 2);
        p += __shfl_xor_sync(0xffffffffu, p, 1);
        sc[k] = p;
    }

    const float NEGINF = __int_as_float(0xff800000);
    float mx = NEGINF;
#pragma unroll
    for (int k = 0; k < KN; k++) {
        sc[k] = s_mask[k] ? NEGINF : sc[k] * 0.1767766952966369f;
        mx = fmaxf(mx, sc[k]);
    }
    float sum = 0.0f;
#pragma unroll
    for (int k = 0; k < KN; k++) {
        sc[k] = __expf(sc[k] - mx);
        sum += sc[k];
    }
    const float inv = 1.0f / sum;

    float accv = 0.0f;
#pragma unroll
    for (int k = 0; k < KN; k++)
        accv = fmaf(sc[k], qkv[(size_t)s_m[k] * 768 + 512 + hofs], accv);

    o[(size_t)n * EE + hofs] = accv * inv;
}

// ---------------------------------------------------------------------------
// LayerNorm over E=256, warp per row, in-place.
// ---------------------------------------------------------------------------
__global__ void __launch_bounds__(256)
ln_kernel(float* __restrict__ X, const float* __restrict__ gamma,
          const float* __restrict__ beta, int rows)
{
    const int row = blockIdx.x * 8 + (threadIdx.x >> 5);
    if (row >= rows) return;
    const int lane = threadIdx.x & 31;
    float* xr = X + (size_t)row * EE;

    float v[8];
    float s = 0.0f;
#pragma unroll
    for (int i = 0; i < 8; i++) {
        v[i] = xr[lane + i * 32];
        s += v[i];
    }
#pragma unroll
    for (int d = 16; d > 0; d >>= 1) s += __shfl_xor_sync(0xffffffffu, s, d);
    const float mean = s * (1.0f / 256.0f);

    float var = 0.0f;
#pragma unroll
    for (int i = 0; i < 8; i++) {
        const float d = v[i] - mean;
        var = fmaf(d, d, var);
    }
#pragma unroll
    for (int d = 16; d > 0; d >>= 1) var += __shfl_xor_sync(0xffffffffu, var, d);
    const float rstd = rsqrtf(var * (1.0f / 256.0f) + 1e-5f);

#pragma unroll
    for (int i = 0; i < 8; i++) {
        const int c = lane + i * 32;
        xr[c] = (v[i] - mean) * rstd * gamma[c] + beta[c];
    }
}

// ---------------------------------------------------------------------------
extern "C" void kernel_launch(void* const* d_in, const int* in_sizes, int n_in,
                              void* d_out, int out_size)
{
    const float* mq    = (const float*)d_in[0];
    const float* Wq    = (const float*)d_in[1];
    const float* bq    = (const float*)d_in[2];
    const float* Wk    = (const float*)d_in[3];
    const float* bk    = (const float*)d_in[4];
    const float* Wv    = (const float*)d_in[5];
    const float* bv    = (const float*)d_in[6];
    const float* Wo    = (const float*)d_in[7];
    const float* bo    = (const float*)d_in[8];
    const float* ln1g  = (const float*)d_in[9];
    const float* ln1b  = (const float*)d_in[10];
    const float* W1    = (const float*)d_in[11];
    const float* b1    = (const float*)d_in[12];
    const float* W2    = (const float*)d_in[13];
    const float* b2    = (const float*)d_in[14];
    const float* ln2g  = (const float*)d_in[15];
    const float* ln2b  = (const float*)d_in[16];
    const void*  bidx  = d_in[17];
    const void*  graph = d_in[18];
    const void*  mask  = d_in[19];

    float* out = (float*)d_out;

    float* qkv; cudaGetSymbolAddress((void**)&qkv, g_qkv);
    float* o;   cudaGetSymbolAddress((void**)&o,   g_o);
    float* x;   cudaGetSymbolAddress((void**)&x,   g_x);
    float* hbuf;cudaGetSymbolAddress((void**)&hbuf,g_h);

    const int M = NTOK;
    const int MB = (M + BM - 1) / BM;   // 431

    // 0) Detect index/mask dtypes and canonicalize
    detect_kernel<<<1, 256>>>(bidx, mask);
    convert_kernel<<<256, 256>>>(bidx, graph, mask);

    // 1) Fused Q/K/V projections (project-then-gather), z selects matrix
    {
        dim3 grid(MB, 2, 3);
        gemm_tc<false, false><<<grid, 256>>>(mq, Wq, Wk, Wv, bq, bk, bv,
                                             qkv, nullptr, M, EE, 768, 256);
    }

    // 2) Attention with gathered K/V rows
    attn_kernel<<<M, 256>>>(qkv, o);

    // 3) Wo projection + residual(mq) -> x, then LN1 in-place
    {
        dim3 grid(MB, 2, 1);
        gemm_tc<true, false><<<grid, 256>>>(o, Wo, Wo, Wo, bo, bo, bo,
                                            x, mq, M, EE, EE, 0);
        ln_kernel<<<(M + 7) / 8, 256>>>(x, ln1g, ln1b, M);
    }

    // 4) FFN1 + exact GELU
    {
        dim3 grid(MB, 8, 1);
        gemm_tc<false, true><<<grid, 256>>>(x, W1, W1, W1, b1, b1, b1,
                                            hbuf, nullptr, M, EE, FF, 0);
    }

    // 5) FFN2 + residual(x) -> out, then LN2 in-place
    {
        dim3 grid(MB, 2, 1);
        gemm_tc<true, false><<<grid, 256>>>(hbuf, W2, W2, W2, b2, b2, b2,
                                            out, x, M, FF, EE, 0);
        ln_kernel<<<(M + 7) / 8, 256>>>(out, ln2g, ln2b, M);
    }
}

// round 7
// speedup vs baseline: 1.6825x; 1.1036x over previous
#include <cuda_runtime.h>
#include <cuda_bf16.h>
#include <math.h>
#include <stdint.h>

// Problem constants
#define QM 8
#define VV 6890
#define KN 16
#define EE 256
#define HH 8
#define DD 32
#define NTOK (QM * VV)          // 55120
#define FF (4 * EE)             // 1024

// GEMM tiling
#define BM 128
#define BN 128
#define BK 32
#define SKP 40                  // smem row stride in halves (32 + 8 pad; 80B = 5*16B)

// Weight pack offsets (elements) in g_wh / g_wl
#define WOFF_Q  0
#define WOFF_K  65536
#define WOFF_V  131072
#define WOFF_O  196608
#define WOFF_1  262144
#define WOFF_2  524288
#define WTOTAL  786432

// Scratch (static device globals; no runtime allocation)
__device__ float g_qkv[(size_t)NTOK * 768];      // [N][q|k|v] fp32 (attn input)
__device__ float g_x[(size_t)NTOK * EE];         // post-LN1 x fp32 (FFN2 residual)
__device__ __nv_bfloat16 g_mqh[(size_t)NTOK * EE], g_mql[(size_t)NTOK * EE];
__device__ __nv_bfloat16 g_oh [(size_t)NTOK * EE], g_ol [(size_t)NTOK * EE];
__device__ __nv_bfloat16 g_xh [(size_t)NTOK * EE], g_xl [(size_t)NTOK * EE];
__device__ __nv_bfloat16 g_hh [(size_t)NTOK * FF], g_hl [(size_t)NTOK * FF];
__device__ __nv_bfloat16 g_wh[WTOTAL], g_wl[WTOTAL];

// Canonicalized index/mask buffers + dtype flags
__device__ int g_idx64;
__device__ int g_mask32;
__device__ int g_cidx[(size_t)NTOK * KN];
__device__ unsigned char g_cmask[(size_t)NTOK * KN];

// ---------------------------------------------------------------------------
// Dtype detection + canonicalization
// ---------------------------------------------------------------------------
__global__ void detect_kernel(const void* bidx, const void* mask)
{
    __shared__ int s_is64, s_m32;
    if (threadIdx.x == 0) { s_is64 = 1; s_m32 = 1; }
    __syncthreads();

    const unsigned long long* b64 = (const unsigned long long*)bidx;
    for (int i = threadIdx.x; i < 1024; i += blockDim.x)
        if (b64[i] >= (1ull << 32)) atomicExch(&s_is64, 0);

    const unsigned int* m32 = (const unsigned int*)mask;
    for (int i = threadIdx.x; i < 1024; i += blockDim.x)
        if (m32[i] > 1u) atomicExch(&s_m32, 0);

    __syncthreads();
    if (threadIdx.x == 0) { g_idx64 = s_is64; g_mask32 = s_m32; }
}

__global__ void convert_kernel(const void* bidx, const void* graph, const void* mask)
{
    const int is64 = g_idx64;
    const int m32  = g_mask32;
    const int total = NTOK * KN;
    for (int i = blockIdx.x * blockDim.x + threadIdx.x; i < total;
         i += gridDim.x * blockDim.x) {
        int b, g;
        if (is64) {
            b = (int)((const long long*)bidx)[i];
            g = (int)((const long long*)graph)[i];
        } else {
            b = ((const int*)bidx)[i];
            g = ((const int*)graph)[i];
        }
        g_cidx[i] = b * VV + g;
        g_cmask[i] = m32 ? (unsigned char)(((const int*)mask)[i] != 0)
                         : ((const unsigned char*)mask)[i];
    }
}

// ---------------------------------------------------------------------------
// fp32 -> split bf16 (hi = bf16(x), lo = bf16(x - hi))
// ---------------------------------------------------------------------------
__device__ __forceinline__ void split_bf16(float x, __nv_bfloat16& h, __nv_bfloat16& l) {
    h = __float2bfloat16(x);
    l = __float2bfloat16(x - __bfloat162float(h));
}

__global__ void cvt_split(const float* __restrict__ src,
                          __nv_bfloat16* __restrict__ H,
                          __nv_bfloat16* __restrict__ L, int n)
{
    for (int i = (blockIdx.x * blockDim.x + threadIdx.x) * 4; i < n;
         i += gridDim.x * blockDim.x * 4) {
        float4 v = *(const float4*)(src + i);
        __nv_bfloat16 h0, h1, h2, h3, l0, l1, l2, l3;
        split_bf16(v.x, h0, l0); split_bf16(v.y, h1, l1);
        split_bf16(v.z, h2, l2); split_bf16(v.w, h3, l3);
        *(__nv_bfloat162*)(H + i)     = __nv_bfloat162(h0, h1);
        *(__nv_bfloat162*)(H + i + 2) = __nv_bfloat162(h2, h3);
        *(__nv_bfloat162*)(L + i)     = __nv_bfloat162(l0, l1);
        *(__nv_bfloat162*)(L + i + 2) = __nv_bfloat162(l2, l3);
    }
}

// ---------------------------------------------------------------------------
// MMA / async-copy helpers
// ---------------------------------------------------------------------------
__device__ __forceinline__ uint32_t smem_u32(const void* p) {
    return (uint32_t)__cvta_generic_to_shared(p);
}
__device__ __forceinline__ void ldsm_x4(uint32_t& r0, uint32_t& r1,
                                        uint32_t& r2, uint32_t& r3, uint32_t addr) {
    asm volatile("ldmatrix.sync.aligned.m8n8.x4.shared.b16 {%0,%1,%2,%3}, [%4];"
                 : "=r"(r0), "=r"(r1), "=r"(r2), "=r"(r3) : "r"(addr));
}
__device__ __forceinline__ void ldsm_x2(uint32_t& r0, uint32_t& r1, uint32_t addr) {
    asm volatile("ldmatrix.sync.aligned.m8n8.x2.shared.b16 {%0,%1}, [%2];"
                 : "=r"(r0), "=r"(r1) : "r"(addr));
}
__device__ __forceinline__ void mma_bf16(float* d, const uint32_t* a, const uint32_t* b) {
    asm volatile("mma.sync.aligned.m16n8k16.row.col.f32.bf16.bf16.f32 "
                 "{%0,%1,%2,%3}, {%4,%5,%6,%7}, {%8,%9}, {%0,%1,%2,%3};"
                 : "+f"(d[0]), "+f"(d[1]), "+f"(d[2]), "+f"(d[3])
                 : "r"(a[0]), "r"(a[1]), "r"(a[2]), "r"(a[3]), "r"(b[0]), "r"(b[1]));
}
__device__ __forceinline__ void cp_async16(void* dst, const void* src, bool pred) {
    const int sz = pred ? 16 : 0;
    asm volatile("cp.async.cg.shared.global [%0], [%1], 16, %2;"
                 :: "r"(smem_u32(dst)), "l"(src), "r"(sz));
}
__device__ __forceinline__ void cp_commit() { asm volatile("cp.async.commit_group;"); }
__device__ __forceinline__ void cp_wait0()  { asm volatile("cp.async.wait_group 0;"); }

__device__ __forceinline__ float gelu_exact(float x) {
    return 0.5f * x * (1.0f + erff(x * 0.7071067811865475f));
}

// ---------------------------------------------------------------------------
// Split-bf16 tensor-core GEMM, pre-converted operands, cp.async loader.
// C[M,*] = A[M,Kd] @ W[Ncols,Kd]^T + bias (+res), optional GELU.
// Outputs: fp32 C (OUTF32) and/or split-bf16 Ch/Cl (OUTBF).
// Grid: (ceil(M/128), Ncols/128, nz). z picks weight slice + bias + out offset.
// ---------------------------------------------------------------------------
template<bool HASRES, bool DOGELU, bool OUTF32, bool OUTBF>
__global__ void __launch_bounds__(256)
gemm_tc(const __nv_bfloat16* __restrict__ Ah, const __nv_bfloat16* __restrict__ Al,
        const __nv_bfloat16* __restrict__ Whb, const __nv_bfloat16* __restrict__ Wlb,
        int wzstride,
        const float* __restrict__ ba, const float* __restrict__ bb,
        const float* __restrict__ bc,
        float* __restrict__ C, __nv_bfloat16* __restrict__ Ch,
        __nv_bfloat16* __restrict__ Cl,
        const float* __restrict__ res,
        int M, int Kd, int ldc, int zstride)
{
    __shared__ __nv_bfloat16 sAh[BM * SKP], sAl[BM * SKP];
    __shared__ __nv_bfloat16 sBh[BN * SKP], sBl[BN * SKP];

    const int z = blockIdx.z;
    const __nv_bfloat16* Wh = Whb + (size_t)z * wzstride;
    const __nv_bfloat16* Wl = Wlb + (size_t)z * wzstride;
    const float* bias = (z == 0) ? ba : (z == 1) ? bb : bc;

    const int tid = threadIdx.x;
    const int lane = tid & 31;
    const int warp = tid >> 5;
    const int wm0 = (warp >> 2) * 64;
    const int wn0 = (warp & 3) * 32;

    const int row0 = blockIdx.x * BM;
    const int wcol0 = blockIdx.y * BN;
    const int outbase = z * zstride;

    float acc[4][4][4];
#pragma unroll
    for (int mi = 0; mi < 4; mi++)
#pragma unroll
        for (int ni = 0; ni < 4; ni++)
#pragma unroll
            for (int r = 0; r < 4; r++) acc[mi][ni][r] = 0.0f;

    const int nIter = Kd / BK;

    // Copy mapping: 512 chunks of 16B (8 halves) per array; thread does c, c+256
    const int r0c = tid >> 2;            // chunk c=tid:   row, chunk col
    const int k0c = (tid & 3) * 8;
    const int r1c = (tid + 256) >> 2;    // chunk c=tid+256
    const int k1c = k0c;                 // same (tid&3)

    // ldmatrix per-thread smem coords
    const int aRow = wm0 + (lane & 15);
    const int aKoff = (lane >> 4) * 8;
    const int bLane = lane & 15;
    const int bRowB = wn0 + (bLane & 7);
    const int bKoff = (bLane >> 3) * 8;

    for (int it = 0; it < nIter; it++) {
        const int kb = it * BK;

        {   // A tiles (guarded), B tiles (Ncols multiple of 128)
            const bool p0 = (row0 + r0c) < M;
            const bool p1 = (row0 + r1c) < M;
            const size_t a0 = (size_t)(row0 + r0c) * Kd + kb + k0c;
            const size_t a1 = (size_t)(row0 + r1c) * Kd + kb + k1c;
            cp_async16(&sAh[r0c * SKP + k0c], Ah + a0, p0);
            cp_async16(&sAh[r1c * SKP + k1c], Ah + a1, p1);
            cp_async16(&sAl[r0c * SKP + k0c], Al + a0, p0);
            cp_async16(&sAl[r1c * SKP + k1c], Al + a1, p1);
            const size_t b0 = (size_t)(wcol0 + r0c) * Kd + kb + k0c;
            const size_t b1 = (size_t)(wcol0 + r1c) * Kd + kb + k1c;
            cp_async16(&sBh[r0c * SKP + k0c], Wh + b0, true);
            cp_async16(&sBh[r1c * SKP + k1c], Wh + b1, true);
            cp_async16(&sBl[r0c * SKP + k0c], Wl + b0, true);
            cp_async16(&sBl[r1c * SKP + k1c], Wl + b1, true);
        }
        cp_commit();
        cp_wait0();
        __syncthreads();

#pragma unroll
        for (int k2 = 0; k2 < BK; k2 += 16) {
            uint32_t ah[4][4], al[4][4], bh[4][2], bl[4][2];
#pragma unroll
            for (int mi = 0; mi < 4; mi++) {
                const int off = ((aRow + mi * 16) * SKP + k2 + aKoff) * 2;
                ldsm_x4(ah[mi][0], ah[mi][1], ah[mi][2], ah[mi][3],
                        smem_u32(sAh) + off);
                ldsm_x4(al[mi][0], al[mi][1], al[mi][2], al[mi][3],
                        smem_u32(sAl) + off);
            }
#pragma unroll
            for (int ni = 0; ni < 4; ni++) {
                const int off = ((bRowB + ni * 8) * SKP + k2 + bKoff) * 2;
                ldsm_x2(bh[ni][0], bh[ni][1], smem_u32(sBh) + off);
                ldsm_x2(bl[ni][0], bl[ni][1], smem_u32(sBl) + off);
            }
#pragma unroll
            for (int mi = 0; mi < 4; mi++)
#pragma unroll
                for (int ni = 0; ni < 4; ni++) {
                    mma_bf16(acc[mi][ni], ah[mi], bh[ni]);
                    mma_bf16(acc[mi][ni], ah[mi], bl[ni]);
                    mma_bf16(acc[mi][ni], al[mi], bh[ni]);
                }
        }
        __syncthreads();
    }

    // ---- epilogue ----
#pragma unroll
    for (int mi = 0; mi < 4; mi++) {
#pragma unroll
        for (int ni = 0; ni < 4; ni++) {
            const int rA = row0 + wm0 + mi * 16 + (lane >> 2);
            const int cw = wcol0 + wn0 + ni * 8 + 2 * (lane & 3);  // bias index
            const int cg = outbase + cw;                           // output col
            const float b0 = bias[cw], b1 = bias[cw + 1];
#pragma unroll
            for (int half = 0; half < 2; half++) {
                const int r = rA + half * 8;
                if (r >= M) continue;
                float v0 = acc[mi][ni][half * 2 + 0] + b0;
                float v1 = acc[mi][ni][half * 2 + 1] + b1;
                if (HASRES) {
                    v0 += res[(size_t)r * ldc + cg];
                    v1 += res[(size_t)r * ldc + cg + 1];
                }
                if (DOGELU) { v0 = gelu_exact(v0); v1 = gelu_exact(v1); }
                if (OUTF32)
                    *(float2*)(C + (size_t)r * ldc + cg) = make_float2(v0, v1);
                if (OUTBF) {
                    __nv_bfloat16 h0, h1, l0, l1;
                    split_bf16(v0, h0, l0); split_bf16(v1, h1, l1);
                    *(__nv_bfloat162*)(Ch + (size_t)r * ldc + cg) = __nv_bfloat162(h0, h1);
                    *(__nv_bfloat162*)(Cl + (size_t)r * ldc + cg) = __nv_bfloat162(l0, l1);
                }
            }
        }
    }
}

// ---------------------------------------------------------------------------
// Attention: one block per token (8 warps = 8 heads); writes split-bf16 o.
// ---------------------------------------------------------------------------
__global__ void __launch_bounds__(256)
attn_kernel(const float* __restrict__ qkv,
            __nv_bfloat16* __restrict__ oh, __nv_bfloat16* __restrict__ ol)
{
    const int n = blockIdx.x;
    __shared__ int s_m[KN];
    __shared__ unsigned char s_mask[KN];

    const int tid = threadIdx.x;
    if (tid < KN) {
        s_m[tid] = g_cidx[(size_t)n * KN + tid];
        s_mask[tid] = g_cmask[(size_t)n * KN + tid];
    }
    __syncthreads();

    const int h = tid >> 5;
    const int lane = tid & 31;
    const int hofs = h * DD + lane;

    const float qv = qkv[(size_t)n * 768 + hofs];

    float sc[KN];
#pragma unroll
    for (int k = 0; k < KN; k++) {
        float p = qv * qkv[(size_t)s_m[k] * 768 + 256 + hofs];
        p += __shfl_xor_sync(0xffffffffu, p, 16);
        p += __shfl_xor_sync(0xffffffffu, p, 8);
        p += __shfl_xor_sync(0xffffffffu, p, 4);
        p += __shfl_xor_sync(0xffffffffu, p, 2);
        p += __shfl_xor_sync(0xffffffffu, p, 1);
        sc[k] = p;
    }

    const float NEGINF = __int_as_float(0xff800000);
    float mx = NEGINF;
#pragma unroll
    for (int k = 0; k < KN; k++) {
        sc[k] = s_mask[k] ? NEGINF : sc[k] * 0.1767766952966369f;
        mx = fmaxf(mx, sc[k]);
    }
    float sum = 0.0f;
#pragma unroll
    for (int k = 0; k < KN; k++) {
        sc[k] = __expf(sc[k] - mx);
        sum += sc[k];
    }
    const float inv = 1.0f / sum;

    float accv = 0.0f;
#pragma unroll
    for (int k = 0; k < KN; k++)
        accv = fmaf(sc[k], qkv[(size_t)s_m[k] * 768 + 512 + hofs], accv);

    const float v = accv * inv;
    __nv_bfloat16 hh, ll;
    split_bf16(v, hh, ll);
    oh[(size_t)n * EE + hofs] = hh;
    ol[(size_t)n * EE + hofs] = ll;
}

// ---------------------------------------------------------------------------
// LayerNorm over E=256, warp per row, in-place fp32; optional split-bf16 out.
// ---------------------------------------------------------------------------
template<bool WRITEBF>
__global__ void __launch_bounds__(256)
ln_kernel(float* __restrict__ X, const float* __restrict__ gamma,
          const float* __restrict__ beta,
          __nv_bfloat16* __restrict__ Xh, __nv_bfloat16* __restrict__ Xl, int rows)
{
    const int row = blockIdx.x * 8 + (threadIdx.x >> 5);
    if (row >= rows) return;
    const int lane = threadIdx.x & 31;
    float* xr = X + (size_t)row * EE;

    float v[8];
    float s = 0.0f;
#pragma unroll
    for (int i = 0; i < 8; i++) {
        v[i] = xr[lane + i * 32];
        s += v[i];
    }
#pragma unroll
    for (int d = 16; d > 0; d >>= 1) s += __shfl_xor_sync(0xffffffffu, s, d);
    const float mean = s * (1.0f / 256.0f);

    float var = 0.0f;
#pragma unroll
    for (int i = 0; i < 8; i++) {
        const float d = v[i] - mean;
        var = fmaf(d, d, var);
    }
#pragma unroll
    for (int d = 16; d > 0; d >>= 1) var += __shfl_xor_sync(0xffffffffu, var, d);
    const float rstd = rsqrtf(var * (1.0f / 256.0f) + 1e-5f);

#pragma unroll
    for (int i = 0; i < 8; i++) {
        const int c = lane + i * 32;
        const float y = (v[i] - mean) * rstd * gamma[c] + beta[c];
        xr[c] = y;
        if (WRITEBF) {
            __nv_bfloat16 h, l;
            split_bf16(y, h, l);
            Xh[(size_t)row * EE + c] = h;
            Xl[(size_t)row * EE + c] = l;
        }
    }
}

// ---------------------------------------------------------------------------
extern "C" void kernel_launch(void* const* d_in, const int* in_sizes, int n_in,
                              void* d_out, int out_size)
{
    const float* mq    = (const float*)d_in[0];
    const float* Wq    = (const float*)d_in[1];
    const float* bq    = (const float*)d_in[2];
    const float* Wk    = (const float*)d_in[3];
    const float* bk    = (const float*)d_in[4];
    const float* Wv    = (const float*)d_in[5];
    const float* bv    = (const float*)d_in[6];
    const float* Wo    = (const float*)d_in[7];
    const float* bo    = (const float*)d_in[8];
    const float* ln1g  = (const float*)d_in[9];
    const float* ln1b  = (const float*)d_in[10];
    const float* W1    = (const float*)d_in[11];
    const float* b1    = (const float*)d_in[12];
    const float* W2    = (const float*)d_in[13];
    const float* b2    = (const float*)d_in[14];
    const float* ln2g  = (const float*)d_in[15];
    const float* ln2b  = (const float*)d_in[16];
    const void*  bidx  = d_in[17];
    const void*  graph = d_in[18];
    const void*  mask  = d_in[19];

    float* out = (float*)d_out;

    float* qkv; cudaGetSymbolAddress((void**)&qkv, g_qkv);
    float* x;   cudaGetSymbolAddress((void**)&x,   g_x);
    __nv_bfloat16 *mqh, *mql, *oh, *ol, *xh, *xl, *hh, *hl, *wh, *wl;
    cudaGetSymbolAddress((void**)&mqh, g_mqh);
    cudaGetSymbolAddress((void**)&mql, g_mql);
    cudaGetSymbolAddress((void**)&oh,  g_oh);
    cudaGetSymbolAddress((void**)&ol,  g_ol);
    cudaGetSymbolAddress((void**)&xh,  g_xh);
    cudaGetSymbolAddress((void**)&xl,  g_xl);
    cudaGetSymbolAddress((void**)&hh,  g_hh);
    cudaGetSymbolAddress((void**)&hl,  g_hl);
    cudaGetSymbolAddress((void**)&wh,  g_wh);
    cudaGetSymbolAddress((void**)&wl,  g_wl);

    const int M = NTOK;
    const int MB = (M + BM - 1) / BM;   // 431

    // 0) Index/mask canonicalization
    detect_kernel<<<1, 256>>>(bidx, mask);
    convert_kernel<<<256, 256>>>(bidx, graph, mask);

    // 0b) One-time split-bf16 conversions (weights + mq)
    cvt_split<<<1024, 256>>>(mq, mqh, mql, NTOK * EE);
    cvt_split<<<64,  256>>>(Wq, wh + WOFF_Q, wl + WOFF_Q, EE * EE);
    cvt_split<<<64,  256>>>(Wk, wh + WOFF_K, wl + WOFF_K, EE * EE);
    cvt_split<<<64,  256>>>(Wv, wh + WOFF_V, wl + WOFF_V, EE * EE);
    cvt_split<<<64,  256>>>(Wo, wh + WOFF_O, wl + WOFF_O, EE * EE);
    cvt_split<<<256, 256>>>(W1, wh + WOFF_1, wl + WOFF_1, FF * EE);
    cvt_split<<<256, 256>>>(W2, wh + WOFF_2, wl + WOFF_2, EE * FF);

    // 1) Fused Q/K/V projections -> qkv fp32
    {
        dim3 grid(MB, 2, 3);
        gemm_tc<false, false, true, false><<<grid, 256>>>(
            mqh, mql, wh, wl, 65536, bq, bk, bv,
            qkv, nullptr, nullptr, nullptr, M, EE, 768, 256);
    }

    // 2) Attention -> split-bf16 o
    attn_kernel<<<M, 256>>>(qkv, oh, ol);

    // 3) Wo projection + residual(mq) -> x fp32; LN1 in-place + split-bf16 x
    {
        dim3 grid(MB, 2, 1);
        gemm_tc<true, false, true, false><<<grid, 256>>>(
            oh, ol, wh + WOFF_O, wl + WOFF_O, 0, bo, bo, bo,
            x, nullptr, nullptr, mq, M, EE, EE, 0);
        ln_kernel<true><<<(M + 7) / 8, 256>>>(x, ln1g, ln1b, xh, xl, M);
    }

    // 4) FFN1 + GELU -> split-bf16 h only
    {
        dim3 grid(MB, 8, 1);
        gemm_tc<false, true, false, true><<<grid, 256>>>(
            xh, xl, wh + WOFF_1, wl + WOFF_1, 0, b1, b1, b1,
            nullptr, hh, hl, nullptr, M, EE, FF, 0);
    }

    // 5) FFN2 + residual(x) -> out fp32; LN2 in-place
    {
        dim3 grid(MB, 2, 1);
        gemm_tc<true, false, true, false><<<grid, 256>>>(
            hh, hl, wh + WOFF_2, wl + WOFF_2, 0, b2, b2, b2,
            out, nullptr, nullptr, x, M, FF, EE, 0);
        ln_kernel<false><<<(M + 7) / 8, 256>>>(out, ln2g, ln2b, nullptr, nullptr, M);
    }
}

// round 8
// speedup vs baseline: 1.7688x; 1.0513x over previous
#include <cuda_runtime.h>
#include <cuda_bf16.h>
#include <math.h>
#include <stdint.h>

// Problem constants
#define QM 8
#define VV 6890
#define KN 16
#define EE 256
#define HH 8
#define DD 32
#define NTOK (QM * VV)          // 55120
#define FF (4 * EE)             // 1024

// GEMM tiling
#define BM 128
#define BN 128
#define BK 16
#define SKP 24                  // smem row stride in halves (16 + 8 pad; 48B rows)

// Weight pack offsets (elements) in g_wh / g_wl
#define WOFF_Q  0
#define WOFF_K  65536
#define WOFF_V  131072
#define WOFF_O  196608
#define WOFF_1  262144
#define WOFF_2  524288
#define WTOTAL  786432

// Scratch (static device globals; no runtime allocation)
__device__ float g_qkv[(size_t)NTOK * 768];      // [N][q|k|v] fp32 (attn input)
__device__ float g_x[(size_t)NTOK * EE];         // post-LN1 x fp32 (FFN2 residual)
__device__ __nv_bfloat16 g_mqh[(size_t)NTOK * EE], g_mql[(size_t)NTOK * EE];
__device__ __nv_bfloat16 g_oh [(size_t)NTOK * EE], g_ol [(size_t)NTOK * EE];
__device__ __nv_bfloat16 g_xh [(size_t)NTOK * EE], g_xl [(size_t)NTOK * EE];
__device__ __nv_bfloat16 g_hh [(size_t)NTOK * FF], g_hl [(size_t)NTOK * FF];
__device__ __nv_bfloat16 g_wh[WTOTAL], g_wl[WTOTAL];

// Canonicalized index/mask buffers + dtype flags
__device__ int g_idx64;
__device__ int g_mask32;
__device__ int g_cidx[(size_t)NTOK * KN];
__device__ unsigned char g_cmask[(size_t)NTOK * KN];

// ---------------------------------------------------------------------------
// Dtype detection + canonicalization
// ---------------------------------------------------------------------------
__global__ void detect_kernel(const void* bidx, const void* mask)
{
    __shared__ int s_is64, s_m32;
    if (threadIdx.x == 0) { s_is64 = 1; s_m32 = 1; }
    __syncthreads();

    const unsigned long long* b64 = (const unsigned long long*)bidx;
    for (int i = threadIdx.x; i < 1024; i += blockDim.x)
        if (b64[i] >= (1ull << 32)) atomicExch(&s_is64, 0);

    const unsigned int* m32 = (const unsigned int*)mask;
    for (int i = threadIdx.x; i < 1024; i += blockDim.x)
        if (m32[i] > 1u) atomicExch(&s_m32, 0);

    __syncthreads();
    if (threadIdx.x == 0) { g_idx64 = s_is64; g_mask32 = s_m32; }
}

__global__ void convert_kernel(const void* bidx, const void* graph, const void* mask)
{
    const int is64 = g_idx64;
    const int m32  = g_mask32;
    const int total = NTOK * KN;
    for (int i = blockIdx.x * blockDim.x + threadIdx.x; i < total;
         i += gridDim.x * blockDim.x) {
        int b, g;
        if (is64) {
            b = (int)((const long long*)bidx)[i];
            g = (int)((const long long*)graph)[i];
        } else {
            b = ((const int*)bidx)[i];
            g = ((const int*)graph)[i];
        }
        g_cidx[i] = b * VV + g;
        g_cmask[i] = m32 ? (unsigned char)(((const int*)mask)[i] != 0)
                         : ((const unsigned char*)mask)[i];
    }
}

// ---------------------------------------------------------------------------
// fp32 -> split bf16
// ---------------------------------------------------------------------------
__device__ __forceinline__ void split_bf16(float x, __nv_bfloat16& h, __nv_bfloat16& l) {
    h = __float2bfloat16(x);
    l = __float2bfloat16(x - __bfloat162float(h));
}

struct CvtBatch {
    const float* src[7];
    __nv_bfloat16* H[7];
    __nv_bfloat16* L[7];
    int n[7];
};

__global__ void cvt_split_all(CvtBatch b)
{
    const int seg = blockIdx.y;
    const float* __restrict__ src = b.src[seg];
    __nv_bfloat16* __restrict__ H = b.H[seg];
    __nv_bfloat16* __restrict__ L = b.L[seg];
    const int n = b.n[seg];
    for (int i = (blockIdx.x * blockDim.x + threadIdx.x) * 4; i < n;
         i += gridDim.x * blockDim.x * 4) {
        float4 v = *(const float4*)(src + i);
        __nv_bfloat16 h0, h1, h2, h3, l0, l1, l2, l3;
        split_bf16(v.x, h0, l0); split_bf16(v.y, h1, l1);
        split_bf16(v.z, h2, l2); split_bf16(v.w, h3, l3);
        *(__nv_bfloat162*)(H + i)     = __nv_bfloat162(h0, h1);
        *(__nv_bfloat162*)(H + i + 2) = __nv_bfloat162(h2, h3);
        *(__nv_bfloat162*)(L + i)     = __nv_bfloat162(l0, l1);
        *(__nv_bfloat162*)(L + i + 2) = __nv_bfloat162(l2, l3);
    }
}

// ---------------------------------------------------------------------------
// MMA / async-copy helpers
// ---------------------------------------------------------------------------
__device__ __forceinline__ uint32_t smem_u32(const void* p) {
    return (uint32_t)__cvta_generic_to_shared(p);
}
__device__ __forceinline__ void ldsm_x4(uint32_t& r0, uint32_t& r1,
                                        uint32_t& r2, uint32_t& r3, uint32_t addr) {
    asm volatile("ldmatrix.sync.aligned.m8n8.x4.shared.b16 {%0,%1,%2,%3}, [%4];"
                 : "=r"(r0), "=r"(r1), "=r"(r2), "=r"(r3) : "r"(addr));
}
__device__ __forceinline__ void ldsm_x2(uint32_t& r0, uint32_t& r1, uint32_t addr) {
    asm volatile("ldmatrix.sync.aligned.m8n8.x2.shared.b16 {%0,%1}, [%2];"
                 : "=r"(r0), "=r"(r1) : "r"(addr));
}
__device__ __forceinline__ void mma_bf16(float* d, const uint32_t* a, const uint32_t* b) {
    asm volatile("mma.sync.aligned.m16n8k16.row.col.f32.bf16.bf16.f32 "
                 "{%0,%1,%2,%3}, {%4,%5,%6,%7}, {%8,%9}, {%0,%1,%2,%3};"
                 : "+f"(d[0]), "+f"(d[1]), "+f"(d[2]), "+f"(d[3])
                 : "r"(a[0]), "r"(a[1]), "r"(a[2]), "r"(a[3]), "r"(b[0]), "r"(b[1]));
}
__device__ __forceinline__ void cp_async16(void* dst, const void* src, bool pred) {
    const int sz = pred ? 16 : 0;
    asm volatile("cp.async.cg.shared.global [%0], [%1], 16, %2;"
                 :: "r"(smem_u32(dst)), "l"(src), "r"(sz));
}
__device__ __forceinline__ void cp_commit() { asm volatile("cp.async.commit_group;"); }
template<int N>
__device__ __forceinline__ void cp_wait() {
    asm volatile("cp.async.wait_group %0;" :: "n"(N));
}

__device__ __forceinline__ float gelu_exact(float x) {
    return 0.5f * x * (1.0f + erff(x * 0.7071067811865475f));
}

// ---------------------------------------------------------------------------
// Split-bf16 tensor-core GEMM, 2-stage cp.async pipeline.
// C[M,*] = A[M,Kd] @ W[Ncols,Kd]^T + bias (+res), optional GELU.
// ---------------------------------------------------------------------------
template<bool HASRES, bool DOGELU, bool OUTF32, bool OUTBF>
__global__ void __launch_bounds__(256)
gemm_tc(const __nv_bfloat16* __restrict__ Ah, const __nv_bfloat16* __restrict__ Al,
        const __nv_bfloat16* __restrict__ Whb, const __nv_bfloat16* __restrict__ Wlb,
        int wzstride,
        const float* __restrict__ ba, const float* __restrict__ bb,
        const float* __restrict__ bc,
        float* __restrict__ C, __nv_bfloat16* __restrict__ Ch,
        __nv_bfloat16* __restrict__ Cl,
        const float* __restrict__ res,
        int M, int Kd, int ldc, int zstride)
{
    __shared__ __nv_bfloat16 sAh[2][BM * SKP], sAl[2][BM * SKP];
    __shared__ __nv_bfloat16 sBh[2][BN * SKP], sBl[2][BN * SKP];

    const int z = blockIdx.z;
    const __nv_bfloat16* Wh = Whb + (size_t)z * wzstride;
    const __nv_bfloat16* Wl = Wlb + (size_t)z * wzstride;
    const float* bias = (z == 0) ? ba : (z == 1) ? bb : bc;

    const int tid = threadIdx.x;
    const int lane = tid & 31;
    const int warp = tid >> 5;
    const int wm0 = (warp >> 2) * 64;
    const int wn0 = (warp & 3) * 32;

    const int row0 = blockIdx.x * BM;
    const int wcol0 = blockIdx.y * BN;
    const int outbase = z * zstride;

    float acc[4][4][4];
#pragma unroll
    for (int mi = 0; mi < 4; mi++)
#pragma unroll
        for (int ni = 0; ni < 4; ni++)
#pragma unroll
            for (int r = 0; r < 4; r++) acc[mi][ni][r] = 0.0f;

    const int nIter = Kd / BK;

    // Loader: 128 rows x 2 chunks(16B) = 256 chunks per plane = 1 per thread
    const int lrow = tid >> 1;
    const int lk   = (tid & 1) * 8;          // halves
    const bool apred = true;                 // row guard computed per use
    (void)apred;

    const int soff = lrow * SKP + lk;
    const bool ap = (row0 + lrow) < M;

    // ldmatrix per-thread smem coords
    const int aRow = wm0 + (lane & 15);
    const int aKoff = (lane >> 4) * 8;
    const int bLane = lane & 15;
    const int bRowB = wn0 + (bLane & 7);
    const int bKoff = (bLane >> 3) * 8;

    // ---- preload stage 0 ----
    {
        const size_t aoff = (size_t)(row0 + lrow) * Kd + lk;
        const size_t boff = (size_t)(wcol0 + lrow) * Kd + lk;
        cp_async16(&sAh[0][soff], Ah + aoff, ap);
        cp_async16(&sAl[0][soff], Al + aoff, ap);
        cp_async16(&sBh[0][soff], Wh + boff, true);
        cp_async16(&sBl[0][soff], Wl + boff, true);
        cp_commit();
    }

    for (int it = 0; it < nIter; it++) {
        const int cur = it & 1;
        const int nxt = cur ^ 1;
        if (it + 1 < nIter) {
            const int kb = (it + 1) * BK;
            const size_t aoff = (size_t)(row0 + lrow) * Kd + kb + lk;
            const size_t boff = (size_t)(wcol0 + lrow) * Kd + kb + lk;
            cp_async16(&sAh[nxt][soff], Ah + aoff, ap);
            cp_async16(&sAl[nxt][soff], Al + aoff, ap);
            cp_async16(&sBh[nxt][soff], Wh + boff, true);
            cp_async16(&sBl[nxt][soff], Wl + boff, true);
            cp_commit();
            cp_wait<1>();
        } else {
            cp_wait<0>();
        }
        __syncthreads();

        // ---- compute one 16-k step on stage cur ----
        uint32_t ah[4][4], al[4][4], bh[4][2], bl[4][2];
#pragma unroll
        for (int mi = 0; mi < 4; mi++) {
            const int off = ((aRow + mi * 16) * SKP + aKoff) * 2;
            ldsm_x4(ah[mi][0], ah[mi][1], ah[mi][2], ah[mi][3],
                    smem_u32(sAh[cur]) + off);
            ldsm_x4(al[mi][0], al[mi][1], al[mi][2], al[mi][3],
                    smem_u32(sAl[cur]) + off);
        }
#pragma unroll
        for (int ni = 0; ni < 4; ni++) {
            const int off = ((bRowB + ni * 8) * SKP + bKoff) * 2;
            ldsm_x2(bh[ni][0], bh[ni][1], smem_u32(sBh[cur]) + off);
            ldsm_x2(bl[ni][0], bl[ni][1], smem_u32(sBl[cur]) + off);
        }
#pragma unroll
        for (int mi = 0; mi < 4; mi++)
#pragma unroll
            for (int ni = 0; ni < 4; ni++) {
                mma_bf16(acc[mi][ni], ah[mi], bh[ni]);
                mma_bf16(acc[mi][ni], ah[mi], bl[ni]);
                mma_bf16(acc[mi][ni], al[mi], bh[ni]);
            }
        __syncthreads();
    }

    // ---- epilogue ----
#pragma unroll
    for (int mi = 0; mi < 4; mi++) {
#pragma unroll
        for (int ni = 0; ni < 4; ni++) {
            const int rA = row0 + wm0 + mi * 16 + (lane >> 2);
            const int cw = wcol0 + wn0 + ni * 8 + 2 * (lane & 3);  // bias index
            const int cg = outbase + cw;                           // output col
            const float b0 = bias[cw], b1 = bias[cw + 1];
#pragma unroll
            for (int half = 0; half < 2; half++) {
                const int r = rA + half * 8;
                if (r >= M) continue;
                float v0 = acc[mi][ni][half * 2 + 0] + b0;
                float v1 = acc[mi][ni][half * 2 + 1] + b1;
                if (HASRES) {
                    v0 += res[(size_t)r * ldc + cg];
                    v1 += res[(size_t)r * ldc + cg + 1];
                }
                if (DOGELU) { v0 = gelu_exact(v0); v1 = gelu_exact(v1); }
                if (OUTF32)
                    *(float2*)(C + (size_t)r * ldc + cg) = make_float2(v0, v1);
                if (OUTBF) {
                    __nv_bfloat16 h0, h1, l0, l1;
                    split_bf16(v0, h0, l0); split_bf16(v1, h1, l1);
                    *(__nv_bfloat162*)(Ch + (size_t)r * ldc + cg) = __nv_bfloat162(h0, h1);
                    *(__nv_bfloat162*)(Cl + (size_t)r * ldc + cg) = __nv_bfloat162(l0, l1);
                }
            }
        }
    }
}

// ---------------------------------------------------------------------------
// Attention: one block per token (8 warps = 8 heads); writes split-bf16 o.
// ---------------------------------------------------------------------------
__global__ void __launch_bounds__(256)
attn_kernel(const float* __restrict__ qkv,
            __nv_bfloat16* __restrict__ oh, __nv_bfloat16* __restrict__ ol)
{
    const int n = blockIdx.x;
    __shared__ int s_m[KN];
    __shared__ unsigned char s_mask[KN];

    const int tid = threadIdx.x;
    if (tid < KN) {
        s_m[tid] = g_cidx[(size_t)n * KN + tid];
        s_mask[tid] = g_cmask[(size_t)n * KN + tid];
    }
    __syncthreads();

    const int h = tid >> 5;
    const int lane = tid & 31;
    const int hofs = h * DD + lane;

    const float qv = qkv[(size_t)n * 768 + hofs];

    float sc[KN];
#pragma unroll
    for (int k = 0; k < KN; k++) {
        float p = qv * qkv[(size_t)s_m[k] * 768 + 256 + hofs];
        p += __shfl_xor_sync(0xffffffffu, p, 16);
        p += __shfl_xor_sync(0xffffffffu, p, 8);
        p += __shfl_xor_sync(0xffffffffu, p, 4);
        p += __shfl_xor_sync(0xffffffffu, p, 2);
        p += __shfl_xor_sync(0xffffffffu, p, 1);
        sc[k] = p;
    }

    const float NEGINF = __int_as_float(0xff800000);
    float mx = NEGINF;
#pragma unroll
    for (int k = 0; k < KN; k++) {
        sc[k] = s_mask[k] ? NEGINF : sc[k] * 0.1767766952966369f;
        mx = fmaxf(mx, sc[k]);
    }
    float sum = 0.0f;
#pragma unroll
    for (int k = 0; k < KN; k++) {
        sc[k] = __expf(sc[k] - mx);
        sum += sc[k];
    }
    const float inv = 1.0f / sum;

    float accv = 0.0f;
#pragma unroll
    for (int k = 0; k < KN; k++)
        accv = fmaf(sc[k], qkv[(size_t)s_m[k] * 768 + 512 + hofs], accv);

    const float v = accv * inv;
    __nv_bfloat16 hh, ll;
    split_bf16(v, hh, ll);
    oh[(size_t)n * EE + hofs] = hh;
    ol[(size_t)n * EE + hofs] = ll;
}

// ---------------------------------------------------------------------------
// LayerNorm over E=256, warp per row, in-place fp32; optional split-bf16 out.
// ---------------------------------------------------------------------------
template<bool WRITEBF>
__global__ void __launch_bounds__(256)
ln_kernel(float* __restrict__ X, const float* __restrict__ gamma,
          const float* __restrict__ beta,
          __nv_bfloat16* __restrict__ Xh, __nv_bfloat16* __restrict__ Xl, int rows)
{
    const int row = blockIdx.x * 8 + (threadIdx.x >> 5);
    if (row >= rows) return;
    const int lane = threadIdx.x & 31;
    float* xr = X + (size_t)row * EE;

    float v[8];
    float s = 0.0f;
#pragma unroll
    for (int i = 0; i < 8; i++) {
        v[i] = xr[lane + i * 32];
        s += v[i];
    }
#pragma unroll
    for (int d = 16; d > 0; d >>= 1) s += __shfl_xor_sync(0xffffffffu, s, d);
    const float mean = s * (1.0f / 256.0f);

    float var = 0.0f;
#pragma unroll
    for (int i = 0; i < 8; i++) {
        const float d = v[i] - mean;
        var = fmaf(d, d, var);
    }
#pragma unroll
    for (int d = 16; d > 0; d >>= 1) var += __shfl_xor_sync(0xffffffffu, var, d);
    const float rstd = rsqrtf(var * (1.0f / 256.0f) + 1e-5f);

#pragma unroll
    for (int i = 0; i < 8; i++) {
        const int c = lane + i * 32;
        const float y = (v[i] - mean) * rstd * gamma[c] + beta[c];
        xr[c] = y;
        if (WRITEBF) {
            __nv_bfloat16 h, l;
            split_bf16(y, h, l);
            Xh[(size_t)row * EE + c] = h;
            Xl[(size_t)row * EE + c] = l;
        }
    }
}

// ---------------------------------------------------------------------------
extern "C" void kernel_launch(void* const* d_in, const int* in_sizes, int n_in,
                              void* d_out, int out_size)
{
    const float* mq    = (const float*)d_in[0];
    const float* Wq    = (const float*)d_in[1];
    const float* bq    = (const float*)d_in[2];
    const float* Wk    = (const float*)d_in[3];
    const float* bk    = (const float*)d_in[4];
    const float* Wv    = (const float*)d_in[5];
    const float* bv    = (const float*)d_in[6];
    const float* Wo    = (const float*)d_in[7];
    const float* bo    = (const float*)d_in[8];
    const float* ln1g  = (const float*)d_in[9];
    const float* ln1b  = (const float*)d_in[10];
    const float* W1    = (const float*)d_in[11];
    const float* b1    = (const float*)d_in[12];
    const float* W2    = (const float*)d_in[13];
    const float* b2    = (const float*)d_in[14];
    const float* ln2g  = (const float*)d_in[15];
    const float* ln2b  = (const float*)d_in[16];
    const void*  bidx  = d_in[17];
    const void*  graph = d_in[18];
    const void*  mask  = d_in[19];

    float* out = (float*)d_out;

    float* qkv; cudaGetSymbolAddress((void**)&qkv, g_qkv);
    float* x;   cudaGetSymbolAddress((void**)&x,   g_x);
    __nv_bfloat16 *mqh, *mql, *oh, *ol, *xh, *xl, *hh, *hl, *wh, *wl;
    cudaGetSymbolAddress((void**)&mqh, g_mqh);
    cudaGetSymbolAddress((void**)&mql, g_mql);
    cudaGetSymbolAddress((void**)&oh,  g_oh);
    cudaGetSymbolAddress((void**)&ol,  g_ol);
    cudaGetSymbolAddress((void**)&xh,  g_xh);
    cudaGetSymbolAddress((void**)&xl,  g_xl);
    cudaGetSymbolAddress((void**)&hh,  g_hh);
    cudaGetSymbolAddress((void**)&hl,  g_hl);
    cudaGetSymbolAddress((void**)&wh,  g_wh);
    cudaGetSymbolAddress((void**)&wl,  g_wl);

    const int M = NTOK;
    const int MB = (M + BM - 1) / BM;   // 431

    // 0) Index/mask canonicalization
    detect_kernel<<<1, 256>>>(bidx, mask);
    convert_kernel<<<256, 256>>>(bidx, graph, mask);

    // 0b) One batched split-bf16 conversion (mq + 6 weights)
    {
        CvtBatch b;
        b.src[0] = mq; b.H[0] = mqh;          b.L[0] = mql;          b.n[0] = NTOK * EE;
        b.src[1] = Wq; b.H[1] = wh + WOFF_Q;  b.L[1] = wl + WOFF_Q;  b.n[1] = EE * EE;
        b.src[2] = Wk; b.H[2] = wh + WOFF_K;  b.L[2] = wl + WOFF_K;  b.n[2] = EE * EE;
        b.src[3] = Wv; b.H[3] = wh + WOFF_V;  b.L[3] = wl + WOFF_V;  b.n[3] = EE * EE;
        b.src[4] = Wo; b.H[4] = wh + WOFF_O;  b.L[4] = wl + WOFF_O;  b.n[4] = EE * EE;
        b.src[5] = W1; b.H[5] = wh + WOFF_1;  b.L[5] = wl + WOFF_1;  b.n[5] = FF * EE;
        b.src[6] = W2; b.H[6] = wh + WOFF_2;  b.L[6] = wl + WOFF_2;  b.n[6] = EE * FF;
        dim3 grid(128, 7);
        cvt_split_all<<<grid, 256>>>(b);
    }

    // 1) Fused Q/K/V projections -> qkv fp32
    {
        dim3 grid(MB, 2, 3);
        gemm_tc<false, false, true, false><<<grid, 256>>>(
            mqh, mql, wh, wl, 65536, bq, bk, bv,
            qkv, nullptr, nullptr, nullptr, M, EE, 768, 256);
    }

    // 2) Attention -> split-bf16 o
    attn_kernel<<<M, 256>>>(qkv, oh, ol);

    // 3) Wo projection + residual(mq) -> x fp32; LN1 + split-bf16 x
    {
        dim3 grid(MB, 2, 1);
        gemm_tc<true, false, true, false><<<grid, 256>>>(
            oh, ol, wh + WOFF_O, wl + WOFF_O, 0, bo, bo, bo,
            x, nullptr, nullptr, mq, M, EE, EE, 0);
        ln_kernel<true><<<(M + 7) / 8, 256>>>(x, ln1g, ln1b, xh, xl, M);
    }

    // 4) FFN1 + GELU -> split-bf16 h only
    {
        dim3 grid(MB, 8, 1);
        gemm_tc<false, true, false, true><<<grid, 256>>>(
            xh, xl, wh + WOFF_1, wl + WOFF_1, 0, b1, b1, b1,
            nullptr, hh, hl, nullptr, M, EE, FF, 0);
    }

    // 5) FFN2 + residual(x) -> out fp32; LN2 in-place
    {
        dim3 grid(MB, 2, 1);
        gemm_tc<true, false, true, false><<<grid, 256>>>(
            hh, hl, wh + WOFF_2, wl + WOFF_2, 0, b2, b2, b2,
            out, nullptr, nullptr, x, M, FF, EE, 0);
        ln_kernel<false><<<(M + 7) / 8, 256>>>(out, ln2g, ln2b, nullptr, nullptr, M);
    }
}

// round 9
// speedup vs baseline: 1.8608x; 1.0520x over previous
#include <cuda_runtime.h>
#include <cuda_bf16.h>
#include <math.h>
#include <stdint.h>

// Problem constants
#define QM 8
#define VV 6890
#define KN 16
#define EE 256
#define HH 8
#define DD 32
#define NTOK (QM * VV)          // 55120
#define FF (4 * EE)             // 1024

// GEMM tiling
#define BM 128
#define BN 128
#define BK 16
#define SKP 24                  // smem row stride in halves (16 + 8 pad; 48B rows)

// Weight pack offsets (elements) in g_wh / g_wl
#define WOFF_Q  0
#define WOFF_K  65536
#define WOFF_V  131072
#define WOFF_O  196608
#define WOFF_1  262144
#define WOFF_2  524288
#define WTOTAL  786432

// Scratch (static device globals; no runtime allocation)
__device__ float g_qkv[(size_t)NTOK * 768];      // [N][q|k|v] fp32 (attn input)
__device__ float g_x[(size_t)NTOK * EE];         // post-LN1 x fp32 (FFN2 residual)
__device__ __nv_bfloat16 g_mqh[(size_t)NTOK * EE], g_mql[(size_t)NTOK * EE];
__device__ __nv_bfloat16 g_oh [(size_t)NTOK * EE], g_ol [(size_t)NTOK * EE];
__device__ __nv_bfloat16 g_xh [(size_t)NTOK * EE], g_xl [(size_t)NTOK * EE];
__device__ __nv_bfloat16 g_hh [(size_t)NTOK * FF], g_hl [(size_t)NTOK * FF];
__device__ __nv_bfloat16 g_wh[WTOTAL], g_wl[WTOTAL];

// Canonicalized index/mask buffers + dtype flags
__device__ int g_idx64;
__device__ int g_mask32;
__device__ int g_cidx[(size_t)NTOK * KN];
__device__ unsigned char g_cmask[(size_t)NTOK * KN];

// ---------------------------------------------------------------------------
// Dtype detection + canonicalization
// ---------------------------------------------------------------------------
__global__ void detect_kernel(const void* bidx, const void* mask)
{
    __shared__ int s_is64, s_m32;
    if (threadIdx.x == 0) { s_is64 = 1; s_m32 = 1; }
    __syncthreads();

    const unsigned long long* b64 = (const unsigned long long*)bidx;
    for (int i = threadIdx.x; i < 1024; i += blockDim.x)
        if (b64[i] >= (1ull << 32)) atomicExch(&s_is64, 0);

    const unsigned int* m32 = (const unsigned int*)mask;
    for (int i = threadIdx.x; i < 1024; i += blockDim.x)
        if (m32[i] > 1u) atomicExch(&s_m32, 0);

    __syncthreads();
    if (threadIdx.x == 0) { g_idx64 = s_is64; g_mask32 = s_m32; }
}

__global__ void convert_kernel(const void* bidx, const void* graph, const void* mask)
{
    const int is64 = g_idx64;
    const int m32  = g_mask32;
    const int total = NTOK * KN;
    for (int i = blockIdx.x * blockDim.x + threadIdx.x; i < total;
         i += gridDim.x * blockDim.x) {
        int b, g;
        if (is64) {
            b = (int)((const long long*)bidx)[i];
            g = (int)((const long long*)graph)[i];
        } else {
            b = ((const int*)bidx)[i];
            g = ((const int*)graph)[i];
        }
        g_cidx[i] = b * VV + g;
        g_cmask[i] = m32 ? (unsigned char)(((const int*)mask)[i] != 0)
                         : ((const unsigned char*)mask)[i];
    }
}

// ---------------------------------------------------------------------------
// fp32 -> split bf16
// ---------------------------------------------------------------------------
__device__ __forceinline__ void split_bf16(float x, __nv_bfloat16& h, __nv_bfloat16& l) {
    h = __float2bfloat16(x);
    l = __float2bfloat16(x - __bfloat162float(h));
}

struct CvtBatch {
    const float* src[7];
    __nv_bfloat16* H[7];
    __nv_bfloat16* L[7];
    int n[7];
};

__global__ void cvt_split_all(CvtBatch b)
{
    const int seg = blockIdx.y;
    const float* __restrict__ src = b.src[seg];
    __nv_bfloat16* __restrict__ H = b.H[seg];
    __nv_bfloat16* __restrict__ L = b.L[seg];
    const int n = b.n[seg];
    for (int i = (blockIdx.x * blockDim.x + threadIdx.x) * 4; i < n;
         i += gridDim.x * blockDim.x * 4) {
        float4 v = *(const float4*)(src + i);
        __nv_bfloat16 h0, h1, h2, h3, l0, l1, l2, l3;
        split_bf16(v.x, h0, l0); split_bf16(v.y, h1, l1);
        split_bf16(v.z, h2, l2); split_bf16(v.w, h3, l3);
        *(__nv_bfloat162*)(H + i)     = __nv_bfloat162(h0, h1);
        *(__nv_bfloat162*)(H + i + 2) = __nv_bfloat162(h2, h3);
        *(__nv_bfloat162*)(L + i)     = __nv_bfloat162(l0, l1);
        *(__nv_bfloat162*)(L + i + 2) = __nv_bfloat162(l2, l3);
    }
}

// ---------------------------------------------------------------------------
// MMA / async-copy helpers
// ---------------------------------------------------------------------------
__device__ __forceinline__ uint32_t smem_u32(const void* p) {
    return (uint32_t)__cvta_generic_to_shared(p);
}
__device__ __forceinline__ void ldsm_x4(uint32_t& r0, uint32_t& r1,
                                        uint32_t& r2, uint32_t& r3, uint32_t addr) {
    asm volatile("ldmatrix.sync.aligned.m8n8.x4.shared.b16 {%0,%1,%2,%3}, [%4];"
                 : "=r"(r0), "=r"(r1), "=r"(r2), "=r"(r3) : "r"(addr));
}
__device__ __forceinline__ void ldsm_x2(uint32_t& r0, uint32_t& r1, uint32_t addr) {
    asm volatile("ldmatrix.sync.aligned.m8n8.x2.shared.b16 {%0,%1}, [%2];"
                 : "=r"(r0), "=r"(r1) : "r"(addr));
}
__device__ __forceinline__ void mma_bf16(float* d, const uint32_t* a, const uint32_t* b) {
    asm volatile("mma.sync.aligned.m16n8k16.row.col.f32.bf16.bf16.f32 "
                 "{%0,%1,%2,%3}, {%4,%5,%6,%7}, {%8,%9}, {%0,%1,%2,%3};"
                 : "+f"(d[0]), "+f"(d[1]), "+f"(d[2]), "+f"(d[3])
                 : "r"(a[0]), "r"(a[1]), "r"(a[2]), "r"(a[3]), "r"(b[0]), "r"(b[1]));
}
__device__ __forceinline__ void cp_async16(void* dst, const void* src, bool pred) {
    const int sz = pred ? 16 : 0;
    asm volatile("cp.async.cg.shared.global [%0], [%1], 16, %2;"
                 :: "r"(smem_u32(dst)), "l"(src), "r"(sz));
}
__device__ __forceinline__ void cp_commit() { asm volatile("cp.async.commit_group;"); }
template<int N>
__device__ __forceinline__ void cp_wait() {
    asm volatile("cp.async.wait_group %0;" :: "n"(N));
}

__device__ __forceinline__ float gelu_exact(float x) {
    return 0.5f * x * (1.0f + erff(x * 0.7071067811865475f));
}

// ---------------------------------------------------------------------------
// Split-bf16 tensor-core GEMM, 2-stage cp.async pipeline, 2 CTAs/SM.
// C[M,*] = A[M,Kd] @ W[Ncols,Kd]^T + bias (+res), optional GELU.
// ---------------------------------------------------------------------------
template<bool HASRES, bool DOGELU, bool OUTF32, bool OUTBF>
__global__ void __launch_bounds__(256, 2)
gemm_tc(const __nv_bfloat16* __restrict__ Ah, const __nv_bfloat16* __restrict__ Al,
        const __nv_bfloat16* __restrict__ Whb, const __nv_bfloat16* __restrict__ Wlb,
        int wzstride,
        const float* __restrict__ ba, const float* __restrict__ bb,
        const float* __restrict__ bc,
        float* __restrict__ C, __nv_bfloat16* __restrict__ Ch,
        __nv_bfloat16* __restrict__ Cl,
        const float* __restrict__ res,
        int M, int Kd, int ldc, int zstride)
{
    __shared__ __nv_bfloat16 sAh[2][BM * SKP], sAl[2][BM * SKP];
    __shared__ __nv_bfloat16 sBh[2][BN * SKP], sBl[2][BN * SKP];

    const int z = blockIdx.z;
    const __nv_bfloat16* Wh = Whb + (size_t)z * wzstride;
    const __nv_bfloat16* Wl = Wlb + (size_t)z * wzstride;
    const float* bias = (z == 0) ? ba : (z == 1) ? bb : bc;

    const int tid = threadIdx.x;
    const int lane = tid & 31;
    const int warp = tid >> 5;
    const int wm0 = (warp >> 2) * 64;
    const int wn0 = (warp & 3) * 32;

    const int row0 = blockIdx.x * BM;
    const int wcol0 = blockIdx.y * BN;
    const int outbase = z * zstride;

    float acc[4][4][4];
#pragma unroll
    for (int mi = 0; mi < 4; mi++)
#pragma unroll
        for (int ni = 0; ni < 4; ni++)
#pragma unroll
            for (int r = 0; r < 4; r++) acc[mi][ni][r] = 0.0f;

    const int nIter = Kd / BK;

    // Loader: 128 rows x 2 chunks(16B) = 256 chunks per plane = 1 per thread
    const int lrow = tid >> 1;
    const int lk   = (tid & 1) * 8;          // halves

    const int soff = lrow * SKP + lk;
    const bool ap = (row0 + lrow) < M;

    // ldmatrix per-thread smem coords
    const int aRow = wm0 + (lane & 15);
    const int aKoff = (lane >> 4) * 8;
    const int bLane = lane & 15;
    const int bRowB = wn0 + (bLane & 7);
    const int bKoff = (bLane >> 3) * 8;

    // ---- preload stage 0 ----
    {
        const size_t aoff = (size_t)(row0 + lrow) * Kd + lk;
        const size_t boff = (size_t)(wcol0 + lrow) * Kd + lk;
        cp_async16(&sAh[0][soff], Ah + aoff, ap);
        cp_async16(&sAl[0][soff], Al + aoff, ap);
        cp_async16(&sBh[0][soff], Wh + boff, true);
        cp_async16(&sBl[0][soff], Wl + boff, true);
        cp_commit();
    }

    for (int it = 0; it < nIter; it++) {
        const int cur = it & 1;
        const int nxt = cur ^ 1;
        if (it + 1 < nIter) {
            const int kb = (it + 1) * BK;
            const size_t aoff = (size_t)(row0 + lrow) * Kd + kb + lk;
            const size_t boff = (size_t)(wcol0 + lrow) * Kd + kb + lk;
            cp_async16(&sAh[nxt][soff], Ah + aoff, ap);
            cp_async16(&sAl[nxt][soff], Al + aoff, ap);
            cp_async16(&sBh[nxt][soff], Wh + boff, true);
            cp_async16(&sBl[nxt][soff], Wl + boff, true);
            cp_commit();
            cp_wait<1>();
        } else {
            cp_wait<0>();
        }
        __syncthreads();

        // ---- compute one 16-k step on stage cur ----
        uint32_t ah[4][4], al[4][4], bh[4][2], bl[4][2];
#pragma unroll
        for (int mi = 0; mi < 4; mi++) {
            const int off = ((aRow + mi * 16) * SKP + aKoff) * 2;
            ldsm_x4(ah[mi][0], ah[mi][1], ah[mi][2], ah[mi][3],
                    smem_u32(sAh[cur]) + off);
            ldsm_x4(al[mi][0], al[mi][1], al[mi][2], al[mi][3],
                    smem_u32(sAl[cur]) + off);
        }
#pragma unroll
        for (int ni = 0; ni < 4; ni++) {
            const int off = ((bRowB + ni * 8) * SKP + bKoff) * 2;
            ldsm_x2(bh[ni][0], bh[ni][1], smem_u32(sBh[cur]) + off);
            ldsm_x2(bl[ni][0], bl[ni][1], smem_u32(sBl[cur]) + off);
        }
#pragma unroll
        for (int mi = 0; mi < 4; mi++)
#pragma unroll
            for (int ni = 0; ni < 4; ni++) {
                mma_bf16(acc[mi][ni], ah[mi], bh[ni]);
                mma_bf16(acc[mi][ni], ah[mi], bl[ni]);
                mma_bf16(acc[mi][ni], al[mi], bh[ni]);
            }
        __syncthreads();
    }

    // ---- epilogue ----
#pragma unroll
    for (int mi = 0; mi < 4; mi++) {
#pragma unroll
        for (int ni = 0; ni < 4; ni++) {
            const int rA = row0 + wm0 + mi * 16 + (lane >> 2);
            const int cw = wcol0 + wn0 + ni * 8 + 2 * (lane & 3);  // bias index
            const int cg = outbase + cw;                           // output col
            const float b0 = bias[cw], b1 = bias[cw + 1];
#pragma unroll
            for (int half = 0; half < 2; half++) {
                const int r = rA + half * 8;
                if (r >= M) continue;
                float v0 = acc[mi][ni][half * 2 + 0] + b0;
                float v1 = acc[mi][ni][half * 2 + 1] + b1;
                if (HASRES) {
                    v0 += res[(size_t)r * ldc + cg];
                    v1 += res[(size_t)r * ldc + cg + 1];
                }
                if (DOGELU) { v0 = gelu_exact(v0); v1 = gelu_exact(v1); }
                if (OUTF32)
                    *(float2*)(C + (size_t)r * ldc + cg) = make_float2(v0, v1);
                if (OUTBF) {
                    __nv_bfloat16 h0, h1, l0, l1;
                    split_bf16(v0, h0, l0); split_bf16(v1, h1, l1);
                    *(__nv_bfloat162*)(Ch + (size_t)r * ldc + cg) = __nv_bfloat162(h0, h1);
                    *(__nv_bfloat162*)(Cl + (size_t)r * ldc + cg) = __nv_bfloat162(l0, l1);
                }
            }
        }
    }
}

// ---------------------------------------------------------------------------
// Attention: one block per token (8 warps = 8 heads); writes split-bf16 o.
// ---------------------------------------------------------------------------
__global__ void __launch_bounds__(256)
attn_kernel(const float* __restrict__ qkv,
            __nv_bfloat16* __restrict__ oh, __nv_bfloat16* __restrict__ ol)
{
    const int n = blockIdx.x;
    __shared__ int s_m[KN];
    __shared__ unsigned char s_mask[KN];

    const int tid = threadIdx.x;
    if (tid < KN) {
        s_m[tid] = g_cidx[(size_t)n * KN + tid];
        s_mask[tid] = g_cmask[(size_t)n * KN + tid];
    }
    __syncthreads();

    const int h = tid >> 5;
    const int lane = tid & 31;
    const int hofs = h * DD + lane;

    const float qv = qkv[(size_t)n * 768 + hofs];

    float sc[KN];
#pragma unroll
    for (int k = 0; k < KN; k++) {
        float p = qv * qkv[(size_t)s_m[k] * 768 + 256 + hofs];
        p += __shfl_xor_sync(0xffffffffu, p, 16);
        p += __shfl_xor_sync(0xffffffffu, p, 8);
        p += __shfl_xor_sync(0xffffffffu, p, 4);
        p += __shfl_xor_sync(0xffffffffu, p, 2);
        p += __shfl_xor_sync(0xffffffffu, p, 1);
        sc[k] = p;
    }

    const float NEGINF = __int_as_float(0xff800000);
    float mx = NEGINF;
#pragma unroll
    for (int k = 0; k < KN; k++) {
        sc[k] = s_mask[k] ? NEGINF : sc[k] * 0.1767766952966369f;
        mx = fmaxf(mx, sc[k]);
    }
    float sum = 0.0f;
#pragma unroll
    for (int k = 0; k < KN; k++) {
        sc[k] = __expf(sc[k] - mx);
        sum += sc[k];
    }
    const float inv = 1.0f / sum;

    float accv = 0.0f;
#pragma unroll
    for (int k = 0; k < KN; k++)
        accv = fmaf(sc[k], qkv[(size_t)s_m[k] * 768 + 512 + hofs], accv);

    const float v = accv * inv;
    __nv_bfloat16 hh, ll;
    split_bf16(v, hh, ll);
    oh[(size_t)n * EE + hofs] = hh;
    ol[(size_t)n * EE + hofs] = ll;
}

// ---------------------------------------------------------------------------
// LayerNorm over E=256, warp per row, in-place fp32; optional split-bf16 out.
// ---------------------------------------------------------------------------
template<bool WRITEBF>
__global__ void __launch_bounds__(256)
ln_kernel(float* __restrict__ X, const float* __restrict__ gamma,
          const float* __restrict__ beta,
          __nv_bfloat16* __restrict__ Xh, __nv_bfloat16* __restrict__ Xl, int rows)
{
    const int row = blockIdx.x * 8 + (threadIdx.x >> 5);
    if (row >= rows) return;
    const int lane = threadIdx.x & 31;
    float* xr = X + (size_t)row * EE;

    float v[8];
    float s = 0.0f;
#pragma unroll
    for (int i = 0; i < 8; i++) {
        v[i] = xr[lane + i * 32];
        s += v[i];
    }
#pragma unroll
    for (int d = 16; d > 0; d >>= 1) s += __shfl_xor_sync(0xffffffffu, s, d);
    const float mean = s * (1.0f / 256.0f);

    float var = 0.0f;
#pragma unroll
    for (int i = 0; i < 8; i++) {
        const float d = v[i] - mean;
        var = fmaf(d, d, var);
    }
#pragma unroll
    for (int d = 16; d > 0; d >>= 1) var += __shfl_xor_sync(0xffffffffu, var, d);
    const float rstd = rsqrtf(var * (1.0f / 256.0f) + 1e-5f);

#pragma unroll
    for (int i = 0; i < 8; i++) {
        const int c = lane + i * 32;
        const float y = (v[i] - mean) * rstd * gamma[c] + beta[c];
        xr[c] = y;
        if (WRITEBF) {
            __nv_bfloat16 h, l;
            split_bf16(y, h, l);
            Xh[(size_t)row * EE + c] = h;
            Xl[(size_t)row * EE + c] = l;
        }
    }
}

// ---------------------------------------------------------------------------
extern "C" void kernel_launch(void* const* d_in, const int* in_sizes, int n_in,
                              void* d_out, int out_size)
{
    const float* mq    = (const float*)d_in[0];
    const float* Wq    = (const float*)d_in[1];
    const float* bq    = (const float*)d_in[2];
    const float* Wk    = (const float*)d_in[3];
    const float* bk    = (const float*)d_in[4];
    const float* Wv    = (const float*)d_in[5];
    const float* bv    = (const float*)d_in[6];
    const float* Wo    = (const float*)d_in[7];
    const float* bo    = (const float*)d_in[8];
    const float* ln1g  = (const float*)d_in[9];
    const float* ln1b  = (const float*)d_in[10];
    const float* W1    = (const float*)d_in[11];
    const float* b1    = (const float*)d_in[12];
    const float* W2    = (const float*)d_in[13];
    const float* b2    = (const float*)d_in[14];
    const float* ln2g  = (const float*)d_in[15];
    const float* ln2b  = (const float*)d_in[16];
    const void*  bidx  = d_in[17];
    const void*  graph = d_in[18];
    const void*  mask  = d_in[19];

    float* out = (float*)d_out;

    float* qkv; cudaGetSymbolAddress((void**)&qkv, g_qkv);
    float* x;   cudaGetSymbolAddress((void**)&x,   g_x);
    __nv_bfloat16 *mqh, *mql, *oh, *ol, *xh, *xl, *hh, *hl, *wh, *wl;
    cudaGetSymbolAddress((void**)&mqh, g_mqh);
    cudaGetSymbolAddress((void**)&mql, g_mql);
    cudaGetSymbolAddress((void**)&oh,  g_oh);
    cudaGetSymbolAddress((void**)&ol,  g_ol);
    cudaGetSymbolAddress((void**)&xh,  g_xh);
    cudaGetSymbolAddress((void**)&xl,  g_xl);
    cudaGetSymbolAddress((void**)&hh,  g_hh);
    cudaGetSymbolAddress((void**)&hl,  g_hl);
    cudaGetSymbolAddress((void**)&wh,  g_wh);
    cudaGetSymbolAddress((void**)&wl,  g_wl);

    const int M = NTOK;
    const int MB = (M + BM - 1) / BM;   // 431

    // 0) Index/mask canonicalization
    detect_kernel<<<1, 256>>>(bidx, mask);
    convert_kernel<<<256, 256>>>(bidx, graph, mask);

    // 0b) One batched split-bf16 conversion (mq + 6 weights)
    {
        CvtBatch b;
        b.src[0] = mq; b.H[0] = mqh;          b.L[0] = mql;          b.n[0] = NTOK * EE;
        b.src[1] = Wq; b.H[1] = wh + WOFF_Q;  b.L[1] = wl + WOFF_Q;  b.n[1] = EE * EE;
        b.src[2] = Wk; b.H[2] = wh + WOFF_K;  b.L[2] = wl + WOFF_K;  b.n[2] = EE * EE;
        b.src[3] = Wv; b.H[3] = wh + WOFF_V;  b.L[3] = wl + WOFF_V;  b.n[3] = EE * EE;
        b.src[4] = Wo; b.H[4] = wh + WOFF_O;  b.L[4] = wl + WOFF_O;  b.n[4] = EE * EE;
        b.src[5] = W1; b.H[5] = wh + WOFF_1;  b.L[5] = wl + WOFF_1;  b.n[5] = FF * EE;
        b.src[6] = W2; b.H[6] = wh + WOFF_2;  b.L[6] = wl + WOFF_2;  b.n[6] = EE * FF;
        dim3 grid(128, 7);
        cvt_split_all<<<grid, 256>>>(b);
    }

    // 1) Fused Q/K/V projections -> qkv fp32
    {
        dim3 grid(MB, 2, 3);
        gemm_tc<false, false, true, false><<<grid, 256>>>(
            mqh, mql, wh, wl, 65536, bq, bk, bv,
            qkv, nullptr, nullptr, nullptr, M, EE, 768, 256);
    }

    // 2) Attention -> split-bf16 o
    attn_kernel<<<M, 256>>>(qkv, oh, ol);

    // 3) Wo projection + residual(mq) -> x fp32; LN1 + split-bf16 x
    {
        dim3 grid(MB, 2, 1);
        gemm_tc<true, false, true, false><<<grid, 256>>>(
            oh, ol, wh + WOFF_O, wl + WOFF_O, 0, bo, bo, bo,
            x, nullptr, nullptr, mq, M, EE, EE, 0);
        ln_kernel<true><<<(M + 7) / 8, 256>>>(x, ln1g, ln1b, xh, xl, M);
    }

    // 4) FFN1 + GELU -> split-bf16 h only
    {
        dim3 grid(MB, 8, 1);
        gemm_tc<false, true, false, true><<<grid, 256>>>(
            xh, xl, wh + WOFF_1, wl + WOFF_1, 0, b1, b1, b1,
            nullptr, hh, hl, nullptr, M, EE, FF, 0);
    }

    // 5) FFN2 + residual(x) -> out fp32; LN2 in-place
    {
        dim3 grid(MB, 2, 1);
        gemm_tc<true, false, true, false><<<grid, 256>>>(
            hh, hl, wh + WOFF_2, wl + WOFF_2, 0, b2, b2, b2,
            out, nullptr, nullptr, x, M, FF, EE, 0);
        ln_kernel<false><<<(M + 7) / 8, 256>>>(out, ln2g, ln2b, nullptr, nullptr, M);
    }
}

// round 10
// speedup vs baseline: 1.9338x; 1.0393x over previous
#include <cuda_runtime.h>
#include <cuda_bf16.h>
#include <math.h>
#include <stdint.h>

// Problem constants
#define QM 8
#define VV 6890
#define KN 16
#define EE 256
#define HH 8
#define DD 32
#define NTOK (QM * VV)          // 55120
#define FF (4 * EE)             // 1024

// GEMM tiling
#define BM 128
#define BN 128
#define BK 16
#define SKP 24                  // smem row stride in halves (16 + 8 pad; 48B rows)
#define PLANE (BM * SKP)        // halves per plane (3072)
#define STAGE_BYTES (4 * PLANE * 2)   // 24576 B per stage (Ah,Al,Bh,Bl)
#define NSTAGE 3
#define SMEM_BYTES (NSTAGE * STAGE_BYTES)  // 73728 B

// Weight pack offsets (elements) in g_wh / g_wl
#define WOFF_Q  0
#define WOFF_K  65536
#define WOFF_V  131072
#define WOFF_O  196608
#define WOFF_1  262144
#define WOFF_2  524288
#define WTOTAL  786432

// Scratch (static device globals; no runtime allocation)
__device__ float g_qkv[(size_t)NTOK * 768];      // [N][q|k|v] fp32 (attn input)
__device__ float g_x[(size_t)NTOK * EE];         // post-LN1 x fp32 (FFN2 residual)
__device__ __nv_bfloat16 g_mqh[(size_t)NTOK * EE], g_mql[(size_t)NTOK * EE];
__device__ __nv_bfloat16 g_oh [(size_t)NTOK * EE], g_ol [(size_t)NTOK * EE];
__device__ __nv_bfloat16 g_xh [(size_t)NTOK * EE], g_xl [(size_t)NTOK * EE];
__device__ __nv_bfloat16 g_hh [(size_t)NTOK * FF], g_hl [(size_t)NTOK * FF];
__device__ __nv_bfloat16 g_wh[WTOTAL], g_wl[WTOTAL];

// Canonicalized index/mask buffers + dtype flags
__device__ int g_idx64;
__device__ int g_mask32;
__device__ int g_cidx[(size_t)NTOK * KN];
__device__ unsigned char g_cmask[(size_t)NTOK * KN];

// ---------------------------------------------------------------------------
// Dtype detection + canonicalization
// ---------------------------------------------------------------------------
__global__ void detect_kernel(const void* bidx, const void* mask)
{
    __shared__ int s_is64, s_m32;
    if (threadIdx.x == 0) { s_is64 = 1; s_m32 = 1; }
    __syncthreads();

    const unsigned long long* b64 = (const unsigned long long*)bidx;
    for (int i = threadIdx.x; i < 1024; i += blockDim.x)
        if (b64[i] >= (1ull << 32)) atomicExch(&s_is64, 0);

    const unsigned int* m32 = (const unsigned int*)mask;
    for (int i = threadIdx.x; i < 1024; i += blockDim.x)
        if (m32[i] > 1u) atomicExch(&s_m32, 0);

    __syncthreads();
    if (threadIdx.x == 0) { g_idx64 = s_is64; g_mask32 = s_m32; }
}

__global__ void convert_kernel(const void* bidx, const void* graph, const void* mask)
{
    const int is64 = g_idx64;
    const int m32  = g_mask32;
    const int total = NTOK * KN;
    for (int i = blockIdx.x * blockDim.x + threadIdx.x; i < total;
         i += gridDim.x * blockDim.x) {
        int b, g;
        if (is64) {
            b = (int)((const long long*)bidx)[i];
            g = (int)((const long long*)graph)[i];
        } else {
            b = ((const int*)bidx)[i];
            g = ((const int*)graph)[i];
        }
        g_cidx[i] = b * VV + g;
        g_cmask[i] = m32 ? (unsigned char)(((const int*)mask)[i] != 0)
                         : ((const unsigned char*)mask)[i];
    }
}

// ---------------------------------------------------------------------------
// fp32 -> split bf16
// ---------------------------------------------------------------------------
__device__ __forceinline__ void split_bf16(float x, __nv_bfloat16& h, __nv_bfloat16& l) {
    h = __float2bfloat16(x);
    l = __float2bfloat16(x - __bfloat162float(h));
}

struct CvtBatch {
    const float* src[7];
    __nv_bfloat16* H[7];
    __nv_bfloat16* L[7];
    int n[7];
};

__global__ void cvt_split_all(CvtBatch b)
{
    const int seg = blockIdx.y;
    const float* __restrict__ src = b.src[seg];
    __nv_bfloat16* __restrict__ H = b.H[seg];
    __nv_bfloat16* __restrict__ L = b.L[seg];
    const int n = b.n[seg];
    for (int i = (blockIdx.x * blockDim.x + threadIdx.x) * 4; i < n;
         i += gridDim.x * blockDim.x * 4) {
        float4 v = *(const float4*)(src + i);
        __nv_bfloat16 h0, h1, h2, h3, l0, l1, l2, l3;
        split_bf16(v.x, h0, l0); split_bf16(v.y, h1, l1);
        split_bf16(v.z, h2, l2); split_bf16(v.w, h3, l3);
        *(__nv_bfloat162*)(H + i)     = __nv_bfloat162(h0, h1);
        *(__nv_bfloat162*)(H + i + 2) = __nv_bfloat162(h2, h3);
        *(__nv_bfloat162*)(L + i)     = __nv_bfloat162(l0, l1);
        *(__nv_bfloat162*)(L + i + 2) = __nv_bfloat162(l2, l3);
    }
}

// ---------------------------------------------------------------------------
// MMA / async-copy helpers
// ---------------------------------------------------------------------------
__device__ __forceinline__ uint32_t smem_u32(const void* p) {
    return (uint32_t)__cvta_generic_to_shared(p);
}
__device__ __forceinline__ void ldsm_x4(uint32_t& r0, uint32_t& r1,
                                        uint32_t& r2, uint32_t& r3, uint32_t addr) {
    asm volatile("ldmatrix.sync.aligned.m8n8.x4.shared.b16 {%0,%1,%2,%3}, [%4];"
                 : "=r"(r0), "=r"(r1), "=r"(r2), "=r"(r3) : "r"(addr));
}
__device__ __forceinline__ void ldsm_x2(uint32_t& r0, uint32_t& r1, uint32_t addr) {
    asm volatile("ldmatrix.sync.aligned.m8n8.x2.shared.b16 {%0,%1}, [%2];"
                 : "=r"(r0), "=r"(r1) : "r"(addr));
}
__device__ __forceinline__ void mma_bf16(float* d, const uint32_t* a, const uint32_t* b) {
    asm volatile("mma.sync.aligned.m16n8k16.row.col.f32.bf16.bf16.f32 "
                 "{%0,%1,%2,%3}, {%4,%5,%6,%7}, {%8,%9}, {%0,%1,%2,%3};"
                 : "+f"(d[0]), "+f"(d[1]), "+f"(d[2]), "+f"(d[3])
                 : "r"(a[0]), "r"(a[1]), "r"(a[2]), "r"(a[3]), "r"(b[0]), "r"(b[1]));
}
__device__ __forceinline__ void cp_async16(uint32_t dst, const void* src, bool pred) {
    const int sz = pred ? 16 : 0;
    asm volatile("cp.async.cg.shared.global [%0], [%1], 16, %2;"
                 :: "r"(dst), "l"(src), "r"(sz));
}
__device__ __forceinline__ void cp_commit() { asm volatile("cp.async.commit_group;"); }
template<int N>
__device__ __forceinline__ void cp_wait() {
    asm volatile("cp.async.wait_group %0;" :: "n"(N));
}

__device__ __forceinline__ float gelu_exact(float x) {
    return 0.5f * x * (1.0f + erff(x * 0.7071067811865475f));
}

// ---------------------------------------------------------------------------
// Split-bf16 tensor-core GEMM, 3-stage cp.async pipeline (1 barrier/iter),
// dynamic smem, 2 CTAs/SM.
// ---------------------------------------------------------------------------
template<bool HASRES, bool DOGELU, bool OUTF32, bool OUTBF>
__global__ void __launch_bounds__(256, 2)
gemm_tc(const __nv_bfloat16* __restrict__ Ah, const __nv_bfloat16* __restrict__ Al,
        const __nv_bfloat16* __restrict__ Whb, const __nv_bfloat16* __restrict__ Wlb,
        int wzstride,
        const float* __restrict__ ba, const float* __restrict__ bb,
        const float* __restrict__ bc,
        float* __restrict__ C, __nv_bfloat16* __restrict__ Ch,
        __nv_bfloat16* __restrict__ Cl,
        const float* __restrict__ res,
        int M, int Kd, int ldc, int zstride)
{
    extern __shared__ __nv_bfloat16 smem[];
    // stage s: Ah at s*4*PLANE, Al +PLANE, Bh +2*PLANE, Bl +3*PLANE

    const int z = blockIdx.z;
    const __nv_bfloat16* Wh = Whb + (size_t)z * wzstride;
    const __nv_bfloat16* Wl = Wlb + (size_t)z * wzstride;
    const float* bias = (z == 0) ? ba : (z == 1) ? bb : bc;

    const int tid = threadIdx.x;
    const int lane = tid & 31;
    const int warp = tid >> 5;
    const int wm0 = (warp >> 2) * 64;
    const int wn0 = (warp & 3) * 32;

    const int row0 = blockIdx.x * BM;
    const int wcol0 = blockIdx.y * BN;
    const int outbase = z * zstride;

    float acc[4][4][4];
#pragma unroll
    for (int mi = 0; mi < 4; mi++)
#pragma unroll
        for (int ni = 0; ni < 4; ni++)
#pragma unroll
            for (int r = 0; r < 4; r++) acc[mi][ni][r] = 0.0f;

    const int nIter = Kd / BK;

    // Loader: 128 rows x 1 chunk(16B) per plane per half-warp pair:
    // 256 chunks per plane, 1 per thread
    const int lrow = tid >> 1;
    const int lk   = (tid & 1) * 8;          // halves
    const int soff = lrow * SKP + lk;
    const bool ap = (row0 + lrow) < M;

    const uint32_t smem_base = smem_u32(smem);

    // ldmatrix per-thread smem coords
    const int aRow = wm0 + (lane & 15);
    const int aKoff = (lane >> 4) * 8;
    const int bLane = lane & 15;
    const int bRowB = wn0 + (bLane & 7);
    const int bKoff = (bLane >> 3) * 8;

    // ---- preload stages 0,1 ----
#pragma unroll
    for (int s = 0; s < 2; s++) {
        if (s < nIter) {
            const int kb = s * BK;
            const uint32_t st = smem_base + s * STAGE_BYTES;
            const size_t aoff = (size_t)(row0 + lrow) * Kd + kb + lk;
            const size_t boff = (size_t)(wcol0 + lrow) * Kd + kb + lk;
            cp_async16(st + soff * 2,                 Ah + aoff, ap);
            cp_async16(st + (PLANE + soff) * 2,       Al + aoff, ap);
            cp_async16(st + (2 * PLANE + soff) * 2,   Wh + boff, true);
            cp_async16(st + (3 * PLANE + soff) * 2,   Wl + boff, true);
        }
        cp_commit();
    }

    int cur = 0;
    for (int it = 0; it < nIter; it++) {
        if (it + 1 < nIter) cp_wait<1>(); else cp_wait<0>();
        __syncthreads();   // stage cur ready; compute(it-1) done on all threads

        // load stage (it+2)%3 (the one freed by compute(it-1))
        if (it + 2 < nIter) {
            int ns = cur + 2; if (ns >= NSTAGE) ns -= NSTAGE;
            const int kb = (it + 2) * BK;
            const uint32_t st = smem_base + ns * STAGE_BYTES;
            const size_t aoff = (size_t)(row0 + lrow) * Kd + kb + lk;
            const size_t boff = (size_t)(wcol0 + lrow) * Kd + kb + lk;
            cp_async16(st + soff * 2,                 Ah + aoff, ap);
            cp_async16(st + (PLANE + soff) * 2,       Al + aoff, ap);
            cp_async16(st + (2 * PLANE + soff) * 2,   Wh + boff, true);
            cp_async16(st + (3 * PLANE + soff) * 2,   Wl + boff, true);
            cp_commit();
        }

        // ---- compute one 16-k step on stage cur ----
        const uint32_t st = smem_base + cur * STAGE_BYTES;
        uint32_t ahf[4][4], alf[4][4], bhf[4][2], blf[4][2];
#pragma unroll
        for (int mi = 0; mi < 4; mi++) {
            const int off = ((aRow + mi * 16) * SKP + aKoff) * 2;
            ldsm_x4(ahf[mi][0], ahf[mi][1], ahf[mi][2], ahf[mi][3], st + off);
            ldsm_x4(alf[mi][0], alf[mi][1], alf[mi][2], alf[mi][3],
                    st + PLANE * 2 + off);
        }
#pragma unroll
        for (int ni = 0; ni < 4; ni++) {
            const int off = ((bRowB + ni * 8) * SKP + bKoff) * 2;
            ldsm_x2(bhf[ni][0], bhf[ni][1], st + 2 * PLANE * 2 + off);
            ldsm_x2(blf[ni][0], blf[ni][1], st + 3 * PLANE * 2 + off);
        }
#pragma unroll
        for (int mi = 0; mi < 4; mi++)
#pragma unroll
            for (int ni = 0; ni < 4; ni++) {
                mma_bf16(acc[mi][ni], ahf[mi], bhf[ni]);
                mma_bf16(acc[mi][ni], ahf[mi], blf[ni]);
                mma_bf16(acc[mi][ni], alf[mi], bhf[ni]);
            }

        cur++; if (cur >= NSTAGE) cur = 0;
    }

    // ---- epilogue ----
#pragma unroll
    for (int mi = 0; mi < 4; mi++) {
#pragma unroll
        for (int ni = 0; ni < 4; ni++) {
            const int rA = row0 + wm0 + mi * 16 + (lane >> 2);
            const int cw = wcol0 + wn0 + ni * 8 + 2 * (lane & 3);  // bias index
            const int cg = outbase + cw;                           // output col
            const float b0 = bias[cw], b1 = bias[cw + 1];
#pragma unroll
            for (int half = 0; half < 2; half++) {
                const int r = rA + half * 8;
                if (r >= M) continue;
                float v0 = acc[mi][ni][half * 2 + 0] + b0;
                float v1 = acc[mi][ni][half * 2 + 1] + b1;
                if (HASRES) {
                    v0 += res[(size_t)r * ldc + cg];
                    v1 += res[(size_t)r * ldc + cg + 1];
                }
                if (DOGELU) { v0 = gelu_exact(v0); v1 = gelu_exact(v1); }
                if (OUTF32)
                    *(float2*)(C + (size_t)r * ldc + cg) = make_float2(v0, v1);
                if (OUTBF) {
                    __nv_bfloat16 h0, h1, l0, l1;
                    split_bf16(v0, h0, l0); split_bf16(v1, h1, l1);
                    *(__nv_bfloat162*)(Ch + (size_t)r * ldc + cg) = __nv_bfloat162(h0, h1);
                    *(__nv_bfloat162*)(Cl + (size_t)r * ldc + cg) = __nv_bfloat162(l0, l1);
                }
            }
        }
    }
}

// ---------------------------------------------------------------------------
// Attention: one block per token (8 warps = 8 heads); writes split-bf16 o.
// ---------------------------------------------------------------------------
__global__ void __launch_bounds__(256)
attn_kernel(const float* __restrict__ qkv,
            __nv_bfloat16* __restrict__ oh, __nv_bfloat16* __restrict__ ol)
{
    const int n = blockIdx.x;
    __shared__ int s_m[KN];
    __shared__ unsigned char s_mask[KN];

    const int tid = threadIdx.x;
    if (tid < KN) {
        s_m[tid] = g_cidx[(size_t)n * KN + tid];
        s_mask[tid] = g_cmask[(size_t)n * KN + tid];
    }
    __syncthreads();

    const int h = tid >> 5;
    const int lane = tid & 31;
    const int hofs = h * DD + lane;

    const float qv = qkv[(size_t)n * 768 + hofs];

    float sc[KN];
#pragma unroll
    for (int k = 0; k < KN; k++) {
        float p = qv * qkv[(size_t)s_m[k] * 768 + 256 + hofs];
        p += __shfl_xor_sync(0xffffffffu, p, 16);
        p += __shfl_xor_sync(0xffffffffu, p, 8);
        p += __shfl_xor_sync(0xffffffffu, p, 4);
        p += __shfl_xor_sync(0xffffffffu, p, 2);
        p += __shfl_xor_sync(0xffffffffu, p, 1);
        sc[k] = p;
    }

    const float NEGINF = __int_as_float(0xff800000);
    float mx = NEGINF;
#pragma unroll
    for (int k = 0; k < KN; k++) {
        sc[k] = s_mask[k] ? NEGINF : sc[k] * 0.1767766952966369f;
        mx = fmaxf(mx, sc[k]);
    }
    float sum = 0.0f;
#pragma unroll
    for (int k = 0; k < KN; k++) {
        sc[k] = __expf(sc[k] - mx);
        sum += sc[k];
    }
    const float inv = 1.0f / sum;

    float accv = 0.0f;
#pragma unroll
    for (int k = 0; k < KN; k++)
        accv = fmaf(sc[k], qkv[(size_t)s_m[k] * 768 + 512 + hofs], accv);

    const float v = accv * inv;
    __nv_bfloat16 hh, ll;
    split_bf16(v, hh, ll);
    oh[(size_t)n * EE + hofs] = hh;
    ol[(size_t)n * EE + hofs] = ll;
}

// ---------------------------------------------------------------------------
// LayerNorm over E=256, warp per row, in-place fp32; optional split-bf16 out.
// ---------------------------------------------------------------------------
template<bool WRITEBF>
__global__ void __launch_bounds__(256)
ln_kernel(float* __restrict__ X, const float* __restrict__ gamma,
          const float* __restrict__ beta,
          __nv_bfloat16* __restrict__ Xh, __nv_bfloat16* __restrict__ Xl, int rows)
{
    const int row = blockIdx.x * 8 + (threadIdx.x >> 5);
    if (row >= rows) return;
    const int lane = threadIdx.x & 31;
    float* xr = X + (size_t)row * EE;

    float v[8];
    float s = 0.0f;
#pragma unroll
    for (int i = 0; i < 8; i++) {
        v[i] = xr[lane + i * 32];
        s += v[i];
    }
#pragma unroll
    for (int d = 16; d > 0; d >>= 1) s += __shfl_xor_sync(0xffffffffu, s, d);
    const float mean = s * (1.0f / 256.0f);

    float var = 0.0f;
#pragma unroll
    for (int i = 0; i < 8; i++) {
        const float d = v[i] - mean;
        var = fmaf(d, d, var);
    }
#pragma unroll
    for (int d = 16; d > 0; d >>= 1) var += __shfl_xor_sync(0xffffffffu, var, d);
    const float rstd = rsqrtf(var * (1.0f / 256.0f) + 1e-5f);

#pragma unroll
    for (int i = 0; i < 8; i++) {
        const int c = lane + i * 32;
        const float y = (v[i] - mean) * rstd * gamma[c] + beta[c];
        xr[c] = y;
        if (WRITEBF) {
            __nv_bfloat16 h, l;
            split_bf16(y, h, l);
            Xh[(size_t)row * EE + c] = h;
            Xl[(size_t)row * EE + c] = l;
        }
    }
}

// ---------------------------------------------------------------------------
extern "C" void kernel_launch(void* const* d_in, const int* in_sizes, int n_in,
                              void* d_out, int out_size)
{
    const float* mq    = (const float*)d_in[0];
    const float* Wq    = (const float*)d_in[1];
    const float* bq    = (const float*)d_in[2];
    const float* Wk    = (const float*)d_in[3];
    const float* bk    = (const float*)d_in[4];
    const float* Wv    = (const float*)d_in[5];
    const float* bv    = (const float*)d_in[6];
    const float* Wo    = (const float*)d_in[7];
    const float* bo    = (const float*)d_in[8];
    const float* ln1g  = (const float*)d_in[9];
    const float* ln1b  = (const float*)d_in[10];
    const float* W1    = (const float*)d_in[11];
    const float* b1    = (const float*)d_in[12];
    const float* W2    = (const float*)d_in[13];
    const float* b2    = (const float*)d_in[14];
    const float* ln2g  = (const float*)d_in[15];
    const float* ln2b  = (const float*)d_in[16];
    const void*  bidx  = d_in[17];
    const void*  graph = d_in[18];
    const void*  mask  = d_in[19];

    float* out = (float*)d_out;

    float* qkv; cudaGetSymbolAddress((void**)&qkv, g_qkv);
    float* x;   cudaGetSymbolAddress((void**)&x,   g_x);
    __nv_bfloat16 *mqh, *mql, *oh, *ol, *xh, *xl, *hh, *hl, *wh, *wl;
    cudaGetSymbolAddress((void**)&mqh, g_mqh);
    cudaGetSymbolAddress((void**)&mql, g_mql);
    cudaGetSymbolAddress((void**)&oh,  g_oh);
    cudaGetSymbolAddress((void**)&ol,  g_ol);
    cudaGetSymbolAddress((void**)&xh,  g_xh);
    cudaGetSymbolAddress((void**)&xl,  g_xl);
    cudaGetSymbolAddress((void**)&hh,  g_hh);
    cudaGetSymbolAddress((void**)&hl,  g_hl);
    cudaGetSymbolAddress((void**)&wh,  g_wh);
    cudaGetSymbolAddress((void**)&wl,  g_wl);

    // Allow 72 KB dynamic smem for all gemm_tc instantiations (one-time cost)
    cudaFuncSetAttribute(gemm_tc<false, false, true,  false>,
                         cudaFuncAttributeMaxDynamicSharedMemorySize, SMEM_BYTES);
    cudaFuncSetAttribute(gemm_tc<true,  false, true,  false>,
                         cudaFuncAttributeMaxDynamicSharedMemorySize, SMEM_BYTES);
    cudaFuncSetAttribute(gemm_tc<false, true,  false, true>,
                         cudaFuncAttributeMaxDynamicSharedMemorySize, SMEM_BYTES);

    const int M = NTOK;
    const int MB = (M + BM - 1) / BM;   // 431

    // 0) Index/mask canonicalization
    detect_kernel<<<1, 256>>>(bidx, mask);
    convert_kernel<<<256, 256>>>(bidx, graph, mask);

    // 0b) One batched split-bf16 conversion (mq + 6 weights)
    {
        CvtBatch b;
        b.src[0] = mq; b.H[0] = mqh;          b.L[0] = mql;          b.n[0] = NTOK * EE;
        b.src[1] = Wq; b.H[1] = wh + WOFF_Q;  b.L[1] = wl + WOFF_Q;  b.n[1] = EE * EE;
        b.src[2] = Wk; b.H[2] = wh + WOFF_K;  b.L[2] = wl + WOFF_K;  b.n[2] = EE * EE;
        b.src[3] = Wv; b.H[3] = wh + WOFF_V;  b.L[3] = wl + WOFF_V;  b.n[3] = EE * EE;
        b.src[4] = Wo; b.H[4] = wh + WOFF_O;  b.L[4] = wl + WOFF_O;  b.n[4] = EE * EE;
        b.src[5] = W1; b.H[5] = wh + WOFF_1;  b.L[5] = wl + WOFF_1;  b.n[5] = FF * EE;
        b.src[6] = W2; b.H[6] = wh + WOFF_2;  b.L[6] = wl + WOFF_2;  b.n[6] = EE * FF;
        dim3 grid(128, 7);
        cvt_split_all<<<grid, 256>>>(b);
    }

    // 1) Fused Q/K/V projections -> qkv fp32
    {
        dim3 grid(MB, 2, 3);
        gemm_tc<false, false, true, false><<<grid, 256, SMEM_BYTES>>>(
            mqh, mql, wh, wl, 65536, bq, bk, bv,
            qkv, nullptr, nullptr, nullptr, M, EE, 768, 256);
    }

    // 2) Attention -> split-bf16 o
    attn_kernel<<<M, 256>>>(qkv, oh, ol);

    // 3) Wo projection + residual(mq) -> x fp32; LN1 + split-bf16 x
    {
        dim3 grid(MB, 2, 1);
        gemm_tc<true, false, true, false><<<grid, 256, SMEM_BYTES>>>(
            oh, ol, wh + WOFF_O, wl + WOFF_O, 0, bo, bo, bo,
            x, nullptr, nullptr, mq, M, EE, EE, 0);
        ln_kernel<true><<<(M + 7) / 8, 256>>>(x, ln1g, ln1b, xh, xl, M);
    }

    // 4) FFN1 + GELU -> split-bf16 h only
    {
        dim3 grid(MB, 8, 1);
        gemm_tc<false, true, false, true><<<grid, 256, SMEM_BYTES>>>(
            xh, xl, wh + WOFF_1, wl + WOFF_1, 0, b1, b1, b1,
            nullptr, hh, hl, nullptr, M, EE, FF, 0);
    }

    // 5) FFN2 + residual(x) -> out fp32; LN2 in-place
    {
        dim3 grid(MB, 2, 1);
        gemm_tc<true, false, true, false><<<grid, 256, SMEM_BYTES>>>(
            hh, hl, wh + WOFF_2, wl + WOFF_2, 0, b2, b2, b2,
            out, nullptr, nullptr, x, M, FF, EE, 0);
        ln_kernel<false><<<(M + 7) / 8, 256>>>(out, ln2g, ln2b, nullptr, nullptr, M);
    }
}